// round 4
// baseline (speedup 1.0000x reference)
#include <cuda_runtime.h>

#define EMBED 1024
#define HEADS 16
#define HEAD_DIM 64
#define BATCH 2
#define SEQ 2048
#define MTOT (BATCH * SEQ)   // 4096

// Scratch for projected Q/K/V in [B,H,N,Dh] layout. Q is pre-scaled by Dh^-0.5.
__device__ float g_q[BATCH * HEADS * SEQ * HEAD_DIM];
__device__ float g_k[BATCH * HEADS * SEQ * HEAD_DIM];
__device__ float g_v[BATCH * HEADS * SEQ * HEAD_DIM];

__device__ __forceinline__ unsigned f2tf(float x) {
    unsigned r;
    asm("cvt.rna.tf32.f32 %0, %1;" : "=r"(r) : "f"(x));
    return r;
}

__device__ __forceinline__ void mma_tf32(float c[4],
                                         unsigned a0, unsigned a1, unsigned a2, unsigned a3,
                                         unsigned b0, unsigned b1) {
    asm volatile(
        "mma.sync.aligned.m16n8k8.row.col.f32.tf32.tf32.f32 "
        "{%0,%1,%2,%3},{%4,%5,%6,%7},{%8,%9},{%0,%1,%2,%3};"
        : "+f"(c[0]), "+f"(c[1]), "+f"(c[2]), "+f"(c[3])
        : "r"(a0), "r"(a1), "r"(a2), "r"(a3), "r"(b0), "r"(b1));
}

// ============================================================================
// Stage A: QKV projection.  Y[m,o] = sum_e X[m,e] * W[o,e] + b[o]
// Block tile 128(M) x 128(N), K-tile 32. 8 warps (4x2). tf32 mma.
// Writes to g_q/g_k/g_v in [B,H,N,Dh] order; q scaled by 1/8.
// ============================================================================
#define GBK 32
#define ASTR 36   // smem row stride (floats): (4g+t) bank pattern conflict-free

__global__ void __launch_bounds__(256, 1) qkv_gemm_kernel(
    const float* __restrict__ Xq, const float* __restrict__ Xk, const float* __restrict__ Xv,
    const float* __restrict__ Wq, const float* __restrict__ bq,
    const float* __restrict__ Wk, const float* __restrict__ bk,
    const float* __restrict__ Wv, const float* __restrict__ bv)
{
    __shared__ unsigned sA[128 * ASTR];
    __shared__ unsigned sB[128 * ASTR];

    const int z = blockIdx.z;
    const float* X    = (z == 0) ? Xq : (z == 1) ? Xk : Xv;
    const float* W    = (z == 0) ? Wq : (z == 1) ? Wk : Wv;
    const float* bias = (z == 0) ? bq : (z == 1) ? bk : bv;
    float* dst        = (z == 0) ? g_q : (z == 1) ? g_k : g_v;
    const float scale = (z == 0) ? 0.125f : 1.0f;   // HEAD_DIM^-0.5 = 1/8

    const int rowBase = blockIdx.y * 128;
    const int colBase = blockIdx.x * 128;
    const int tid  = threadIdx.x;
    const int warp = tid >> 5, lane = tid & 31;
    const int wm = warp >> 1, wn = warp & 1;
    const int g = lane >> 2, t = lane & 3;

    float C[2][8][4];
#pragma unroll
    for (int i = 0; i < 2; i++)
#pragma unroll
        for (int j = 0; j < 8; j++)
#pragma unroll
            for (int k = 0; k < 4; k++) C[i][j][k] = 0.f;

    for (int k0 = 0; k0 < EMBED; k0 += GBK) {
        // Load A tile: X[rowBase..+127][k0..+31]  (1024 float4, 4 per thread)
#pragma unroll
        for (int i = 0; i < 4; i++) {
            int idx = tid + i * 256;
            int r = idx >> 3;
            int c4 = (idx & 7) * 4;
            float4 v = *(const float4*)(X + (size_t)(rowBase + r) * EMBED + k0 + c4);
            unsigned* p = &sA[r * ASTR + c4];
            p[0] = f2tf(v.x); p[1] = f2tf(v.y); p[2] = f2tf(v.z); p[3] = f2tf(v.w);
        }
        // Load B tile: W[colBase..+127][k0..+31]
#pragma unroll
        for (int i = 0; i < 4; i++) {
            int idx = tid + i * 256;
            int r = idx >> 3;
            int c4 = (idx & 7) * 4;
            float4 v = *(const float4*)(W + (size_t)(colBase + r) * EMBED + k0 + c4);
            unsigned* p = &sB[r * ASTR + c4];
            p[0] = f2tf(v.x); p[1] = f2tf(v.y); p[2] = f2tf(v.z); p[3] = f2tf(v.w);
        }
        __syncthreads();

#pragma unroll
        for (int kk = 0; kk < GBK; kk += 8) {
            unsigned a[2][4];
#pragma unroll
            for (int mt = 0; mt < 2; mt++) {
                int r0 = wm * 32 + mt * 16;
                a[mt][0] = sA[(r0 + g)     * ASTR + kk + t];
                a[mt][1] = sA[(r0 + g + 8) * ASTR + kk + t];
                a[mt][2] = sA[(r0 + g)     * ASTR + kk + t + 4];
                a[mt][3] = sA[(r0 + g + 8) * ASTR + kk + t + 4];
            }
#pragma unroll
            for (int nt = 0; nt < 8; nt++) {
                int n0 = wn * 64 + nt * 8;
                unsigned b0 = sB[(n0 + g) * ASTR + kk + t];
                unsigned b1 = sB[(n0 + g) * ASTR + kk + t + 4];
                mma_tf32(C[0][nt], a[0][0], a[0][1], a[0][2], a[0][3], b0, b1);
                mma_tf32(C[1][nt], a[1][0], a[1][1], a[1][2], a[1][3], b0, b1);
            }
        }
        __syncthreads();
    }

    // Epilogue: bias, scale, scatter into [B,H,N,Dh]
#pragma unroll
    for (int mt = 0; mt < 2; mt++) {
#pragma unroll
        for (int nt = 0; nt < 8; nt++) {
#pragma unroll
            for (int e = 0; e < 4; e++) {
                int row = rowBase + wm * 32 + mt * 16 + g + ((e >= 2) ? 8 : 0);
                int col = colBase + wn * 64 + nt * 8 + 2 * t + (e & 1);
                float val = (C[mt][nt][e] + bias[col]) * scale;
                int b = row >> 11;          // / SEQ
                int n = row & (SEQ - 1);
                int h = col >> 6;           // / HEAD_DIM
                int d = col & 63;
                dst[(((size_t)(b * HEADS + h)) * SEQ + n) * HEAD_DIM + d] = val;
            }
        }
    }
}

// ============================================================================
// Stage B: flash attention. One CTA = one (b, h, 128 query rows).
// 16 key tiles of 128. S via tf32 mma -> smem -> online softmax -> P (tf32)
// -> PV via tf32 mma, O in registers.
// ============================================================================
#define QSTR 68    // sQ/sK stride: (4g+t) pattern conflict-free
#define VSTR 72    // sV stride: (8t+g) pattern conflict-free
#define PSTR 132   // sP stride: 132%32==4 -> conflict-free A-fragment reads

#define SQ_OFF 0
#define SK_OFF (128 * QSTR)                    // 8704
#define SV_OFF (SK_OFF + 128 * QSTR)          // 17408
#define SP_OFF (SV_OFF + 128 * VSTR)          // 26624
#define MS_OFF (SP_OFF + 128 * PSTR)          // 43520
#define LS_OFF (MS_OFF + 128)
#define FS_OFF (LS_OFF + 128)
#define SMEM_FLOATS (FS_OFF + 128)            // 43904 floats = 175616 B

__global__ void __launch_bounds__(256, 1) attn_kernel(float* __restrict__ out)
{
    extern __shared__ float smem[];
    unsigned* sQ  = (unsigned*)(smem + SQ_OFF);
    unsigned* sK  = (unsigned*)(smem + SK_OFF);
    unsigned* sV  = (unsigned*)(smem + SV_OFF);
    float*    sP  = smem + SP_OFF;
    unsigned* sPu = (unsigned*)sP;
    float* m_s = smem + MS_OFF;
    float* l_s = smem + LS_OFF;
    float* f_s = smem + FS_OFF;

    const int qtile = blockIdx.x;
    const int h = blockIdx.y;
    const int b = blockIdx.z;
    const int bh = b * HEADS + h;
    const float* Qg = g_q + (size_t)bh * SEQ * HEAD_DIM;
    const float* Kg = g_k + (size_t)bh * SEQ * HEAD_DIM;
    const float* Vg = g_v + (size_t)bh * SEQ * HEAD_DIM;

    const int tid = threadIdx.x, warp = tid >> 5, lane = tid & 31;
    const int wm = warp >> 1, wn = warp & 1;
    const int g = lane >> 2, t = lane & 3;
    const int qbase = qtile * 128;

    // Load Q tile (128 x 64), tf32-rounded
#pragma unroll
    for (int i = 0; i < 8; i++) {
        int idx = tid + i * 256;          // 2048 float4
        int r = idx >> 4;
        int c4 = (idx & 15) * 4;
        float4 v = *(const float4*)(Qg + (size_t)(qbase + r) * HEAD_DIM + c4);
        unsigned* p = &sQ[r * QSTR + c4];
        p[0] = f2tf(v.x); p[1] = f2tf(v.y); p[2] = f2tf(v.z); p[3] = f2tf(v.w);
    }
    if (tid < 128) { m_s[tid] = -1e30f; l_s[tid] = 0.f; }

    float O[2][4][4];
#pragma unroll
    for (int i = 0; i < 2; i++)
#pragma unroll
        for (int j = 0; j < 4; j++)
#pragma unroll
            for (int k = 0; k < 4; k++) O[i][j][k] = 0.f;

    for (int kt = 0; kt < SEQ / 128; kt++) {
        __syncthreads();   // prior-iter PV (sP,sV) and S (sK) reads complete
        const int kbase = kt * 128;
        // Load K and V tiles (128 x 64 each)
#pragma unroll
        for (int i = 0; i < 8; i++) {
            int idx = tid + i * 256;
            int r = idx >> 4;
            int c4 = (idx & 15) * 4;
            float4 v = *(const float4*)(Kg + (size_t)(kbase + r) * HEAD_DIM + c4);
            unsigned* p = &sK[r * QSTR + c4];
            p[0] = f2tf(v.x); p[1] = f2tf(v.y); p[2] = f2tf(v.z); p[3] = f2tf(v.w);
            float4 w = *(const float4*)(Vg + (size_t)(kbase + r) * HEAD_DIM + c4);
            unsigned* q = &sV[r * VSTR + c4];
            q[0] = f2tf(w.x); q[1] = f2tf(w.y); q[2] = f2tf(w.z); q[3] = f2tf(w.w);
        }
        __syncthreads();

        // S = Q * K^T : warp covers rows wm*32..+31, cols wn*64..+63
        float Sc[2][8][4];
#pragma unroll
        for (int i = 0; i < 2; i++)
#pragma unroll
            for (int j = 0; j < 8; j++)
#pragma unroll
                for (int k = 0; k < 4; k++) Sc[i][j][k] = 0.f;

#pragma unroll
        for (int kk = 0; kk < HEAD_DIM; kk += 8) {
            unsigned a[2][4];
#pragma unroll
            for (int mt = 0; mt < 2; mt++) {
                int r0 = wm * 32 + mt * 16;
                a[mt][0] = sQ[(r0 + g)     * QSTR + kk + t];
                a[mt][1] = sQ[(r0 + g + 8) * QSTR + kk + t];
                a[mt][2] = sQ[(r0 + g)     * QSTR + kk + t + 4];
                a[mt][3] = sQ[(r0 + g + 8) * QSTR + kk + t + 4];
            }
#pragma unroll
            for (int nt = 0; nt < 8; nt++) {
                int n0 = wn * 64 + nt * 8;
                unsigned b0 = sK[(n0 + g) * QSTR + kk + t];
                unsigned b1 = sK[(n0 + g) * QSTR + kk + t + 4];
                mma_tf32(Sc[0][nt], a[0][0], a[0][1], a[0][2], a[0][3], b0, b1);
                mma_tf32(Sc[1][nt], a[1][0], a[1][1], a[1][2], a[1][3], b0, b1);
            }
        }
        // Spill S to smem (fp32)
#pragma unroll
        for (int mt = 0; mt < 2; mt++)
#pragma unroll
            for (int nt = 0; nt < 8; nt++)
#pragma unroll
                for (int e = 0; e < 4; e++) {
                    int row = wm * 32 + mt * 16 + g + ((e >= 2) ? 8 : 0);
                    int col = wn * 64 + nt * 8 + 2 * t + (e & 1);
                    sP[row * PSTR + col] = Sc[mt][nt][e];
                }
        __syncthreads();

        // Online softmax: warp w handles rows w*16 .. w*16+15 (full 128 cols)
        for (int rr = 0; rr < 16; rr++) {
            int row = warp * 16 + rr;
            float x0 = sP[row * PSTR + lane];
            float x1 = sP[row * PSTR + lane + 32];
            float x2 = sP[row * PSTR + lane + 64];
            float x3 = sP[row * PSTR + lane + 96];
            float mx = fmaxf(fmaxf(x0, x1), fmaxf(x2, x3));
#pragma unroll
            for (int off = 16; off > 0; off >>= 1)
                mx = fmaxf(mx, __shfl_xor_sync(0xFFFFFFFFu, mx, off));
            float mold = m_s[row];
            float mnew = fmaxf(mold, mx);
            float p0 = __expf(x0 - mnew);
            float p1 = __expf(x1 - mnew);
            float p2 = __expf(x2 - mnew);
            float p3 = __expf(x3 - mnew);
            float s = p0 + p1 + p2 + p3;
#pragma unroll
            for (int off = 16; off > 0; off >>= 1)
                s += __shfl_xor_sync(0xFFFFFFFFu, s, off);
            sPu[row * PSTR + lane]      = f2tf(p0);
            sPu[row * PSTR + lane + 32] = f2tf(p1);
            sPu[row * PSTR + lane + 64] = f2tf(p2);
            sPu[row * PSTR + lane + 96] = f2tf(p3);
            if (lane == 0) {
                float f = __expf(mold - mnew);
                f_s[row] = f;
                l_s[row] = l_s[row] * f + s;
                m_s[row] = mnew;
            }
        }
        __syncthreads();

        // Rescale O by per-row correction factor
        float f0[2], f1[2];
#pragma unroll
        for (int mt = 0; mt < 2; mt++) {
            int r0 = wm * 32 + mt * 16;
            f0[mt] = f_s[r0 + g];
            f1[mt] = f_s[r0 + g + 8];
        }
#pragma unroll
        for (int mt = 0; mt < 2; mt++)
#pragma unroll
            for (int nt = 0; nt < 4; nt++)
#pragma unroll
                for (int e = 0; e < 4; e++)
                    O[mt][nt][e] *= (e >= 2) ? f1[mt] : f0[mt];

        // O += P * V : warp covers rows wm*32..+31, cols (d) wn*32..+31
#pragma unroll
        for (int kk = 0; kk < 128; kk += 8) {
            unsigned a[2][4];
#pragma unroll
            for (int mt = 0; mt < 2; mt++) {
                int r0 = wm * 32 + mt * 16;
                a[mt][0] = sPu[(r0 + g)     * PSTR + kk + t];
                a[mt][1] = sPu[(r0 + g + 8) * PSTR + kk + t];
                a[mt][2] = sPu[(r0 + g)     * PSTR + kk + t + 4];
                a[mt][3] = sPu[(r0 + g + 8) * PSTR + kk + t + 4];
            }
#pragma unroll
            for (int nt = 0; nt < 4; nt++) {
                int n0 = wn * 32 + nt * 8;
                unsigned b0 = sV[(kk + t)     * VSTR + n0 + g];
                unsigned b1 = sV[(kk + t + 4) * VSTR + n0 + g];
                mma_tf32(O[0][nt], a[0][0], a[0][1], a[0][2], a[0][3], b0, b1);
                mma_tf32(O[1][nt], a[1][0], a[1][1], a[1][2], a[1][3], b0, b1);
            }
        }
    }

    // Epilogue: O /= l, write [B, N, E] output
    float li0[2], li1[2];
#pragma unroll
    for (int mt = 0; mt < 2; mt++) {
        int r0 = wm * 32 + mt * 16;
        li0[mt] = 1.f / l_s[r0 + g];
        li1[mt] = 1.f / l_s[r0 + g + 8];
    }
#pragma unroll
    for (int mt = 0; mt < 2; mt++)
#pragma unroll
        for (int nt = 0; nt < 4; nt++)
#pragma unroll
            for (int e = 0; e < 4; e++) {
                int n = qbase + wm * 32 + mt * 16 + g + ((e >= 2) ? 8 : 0);
                int d = wn * 32 + nt * 8 + 2 * t + (e & 1);
                float val = O[mt][nt][e] * ((e >= 2) ? li1[mt] : li0[mt]);
                out[((size_t)b * SEQ + n) * EMBED + h * HEAD_DIM + d] = val;
            }
}

extern "C" void kernel_launch(void* const* d_in, const int* in_sizes, int n_in,
                              void* d_out, int out_size)
{
    const float* query = (const float*)d_in[0];
    const float* key   = (const float*)d_in[1];
    const float* value = (const float*)d_in[2];
    const float* Wq = (const float*)d_in[3];
    const float* bq = (const float*)d_in[4];
    const float* Wk = (const float*)d_in[5];
    const float* bk = (const float*)d_in[6];
    const float* Wv = (const float*)d_in[7];
    const float* bv = (const float*)d_in[8];
    float* out = (float*)d_out;

    (void)in_sizes; (void)n_in; (void)out_size;

    // Stage A: QKV projections (z = 0/1/2 -> q/k/v)
    dim3 ggrid(EMBED / 128, MTOT / 128, 3);
    qkv_gemm_kernel<<<ggrid, 256>>>(query, key, value, Wq, bq, Wk, bk, Wv, bv);

    // Stage B: flash attention (needs >48KB dynamic smem)
    cudaFuncSetAttribute(attn_kernel, cudaFuncAttributeMaxDynamicSharedMemorySize,
                         SMEM_FLOATS * (int)sizeof(float));
    dim3 agrid(SEQ / 128, HEADS, BATCH);
    attn_kernel<<<agrid, 256, SMEM_FLOATS * sizeof(float)>>>(out);
}

// round 8
// speedup vs baseline: 1.4735x; 1.4735x over previous
#include <cuda_runtime.h>

#define EMBED 1024
#define HEADS 16
#define HEAD_DIM 64
#define BATCH 2
#define SEQ 2048
#define MTOT (BATCH * SEQ)   // 4096

// Scratch for projected Q/K/V in [B,H,N,Dh] layout. Q is pre-scaled by Dh^-0.5.
__device__ float g_q[BATCH * HEADS * SEQ * HEAD_DIM];
__device__ float g_k[BATCH * HEADS * SEQ * HEAD_DIM];
__device__ float g_v[BATCH * HEADS * SEQ * HEAD_DIM];

__device__ __forceinline__ unsigned f2tf(float x) {
    unsigned r;
    asm("cvt.rna.tf32.f32 %0, %1;" : "=r"(r) : "f"(x));
    return r;
}

__device__ __forceinline__ void mma_tf32(float c[4],
                                         unsigned a0, unsigned a1, unsigned a2, unsigned a3,
                                         unsigned b0, unsigned b1) {
    asm volatile(
        "mma.sync.aligned.m16n8k8.row.col.f32.tf32.tf32.f32 "
        "{%0,%1,%2,%3},{%4,%5,%6,%7},{%8,%9},{%0,%1,%2,%3};"
        : "+f"(c[0]), "+f"(c[1]), "+f"(c[2]), "+f"(c[3])
        : "r"(a0), "r"(a1), "r"(a2), "r"(a3), "r"(b0), "r"(b1));
}

#define CP_ASYNC16(dst_u32, src_ptr) \
    asm volatile("cp.async.ca.shared.global [%0], [%1], 16;" :: "r"(dst_u32), "l"(src_ptr))
#define CP_COMMIT() asm volatile("cp.async.commit_group;")
#define CP_WAIT0()  asm volatile("cp.async.wait_group 0;")

// ============================================================================
// Stage A: QKV projection.  Y[m,o] = sum_e X[m,e] * W[o,e] + b[o]
// 128x128 tile, K-tile 32, cp.async double buffered, 2 CTAs/SM.
// smem holds raw fp32; cvt.rna.tf32 at fragment load. q scaled by 1/8.
// ============================================================================
#define ASTR 36                    // (4g+t) bank pattern conflict-free
#define QKV_TILE (128 * ASTR)      // floats per tile buffer
#define QKV_SMEM (4 * QKV_TILE * sizeof(float))   // 73728 B

__global__ void __launch_bounds__(256, 2) qkv_gemm_kernel(
    const float* __restrict__ Xq, const float* __restrict__ Xk, const float* __restrict__ Xv,
    const float* __restrict__ Wq, const float* __restrict__ bq,
    const float* __restrict__ Wk, const float* __restrict__ bk,
    const float* __restrict__ Wv, const float* __restrict__ bv)
{
    extern __shared__ float smem[];
    float* sAb[2] = { smem,                smem + QKV_TILE };
    float* sBb[2] = { smem + 2 * QKV_TILE, smem + 3 * QKV_TILE };

    const int z = blockIdx.z;
    const float* X    = (z == 0) ? Xq : (z == 1) ? Xk : Xv;
    const float* W    = (z == 0) ? Wq : (z == 1) ? Wk : Wv;
    const float* bias = (z == 0) ? bq : (z == 1) ? bk : bv;
    float* dst        = (z == 0) ? g_q : (z == 1) ? g_k : g_v;
    const float scale = (z == 0) ? 0.125f : 1.0f;   // HEAD_DIM^-0.5 = 1/8

    const int rowBase = blockIdx.y * 128;
    const int colBase = blockIdx.x * 128;
    const int tid  = threadIdx.x;
    const int warp = tid >> 5, lane = tid & 31;
    const int wm = warp >> 1, wn = warp & 1;
    const int g = lane >> 2, t = lane & 3;

    float C[2][8][4];
#pragma unroll
    for (int i = 0; i < 2; i++)
#pragma unroll
        for (int j = 0; j < 8; j++)
#pragma unroll
            for (int k = 0; k < 4; k++) C[i][j][k] = 0.f;

    auto load_tile = [&](int k0, int bi) {
        unsigned sa = (unsigned)__cvta_generic_to_shared(sAb[bi]);
        unsigned sb = (unsigned)__cvta_generic_to_shared(sBb[bi]);
#pragma unroll
        for (int i = 0; i < 4; i++) {
            int idx = tid + i * 256;
            int r = idx >> 3;
            int c4 = (idx & 7) * 4;
            CP_ASYNC16(sa + (r * ASTR + c4) * 4, X + (size_t)(rowBase + r) * EMBED + k0 + c4);
            CP_ASYNC16(sb + (r * ASTR + c4) * 4, W + (size_t)(colBase + r) * EMBED + k0 + c4);
        }
    };

    load_tile(0, 0); CP_COMMIT();

    for (int kt = 0; kt < EMBED / 32; kt++) {
        CP_WAIT0();
        __syncthreads();
        if (kt + 1 < EMBED / 32) { load_tile((kt + 1) * 32, (kt + 1) & 1); CP_COMMIT(); }

        const float* A = sAb[kt & 1];
        const float* B = sBb[kt & 1];

#pragma unroll
        for (int kk = 0; kk < 32; kk += 8) {
            unsigned a[2][4];
#pragma unroll
            for (int mt = 0; mt < 2; mt++) {
                int r0 = wm * 32 + mt * 16;
                a[mt][0] = f2tf(A[(r0 + g)     * ASTR + kk + t]);
                a[mt][1] = f2tf(A[(r0 + g + 8) * ASTR + kk + t]);
                a[mt][2] = f2tf(A[(r0 + g)     * ASTR + kk + t + 4]);
                a[mt][3] = f2tf(A[(r0 + g + 8) * ASTR + kk + t + 4]);
            }
            // Pre-convert all B fragments for this kk step
            unsigned bf[8][2];
#pragma unroll
            for (int nt = 0; nt < 8; nt++) {
                int n0 = wn * 64 + nt * 8;
                bf[nt][0] = f2tf(B[(n0 + g) * ASTR + kk + t]);
                bf[nt][1] = f2tf(B[(n0 + g) * ASTR + kk + t + 4]);
            }
#pragma unroll
            for (int nt = 0; nt < 8; nt++) {
                mma_tf32(C[0][nt], a[0][0], a[0][1], a[0][2], a[0][3], bf[nt][0], bf[nt][1]);
                mma_tf32(C[1][nt], a[1][0], a[1][1], a[1][2], a[1][3], bf[nt][0], bf[nt][1]);
            }
        }
    }

    // Epilogue: bias, scale, scatter into [B,H,N,Dh] (streaming float2 stores)
#pragma unroll
    for (int mt = 0; mt < 2; mt++) {
#pragma unroll
        for (int nt = 0; nt < 8; nt++) {
            int col = colBase + wn * 64 + nt * 8 + 2 * t;
            float b0v = bias[col], b1v = bias[col + 1];
            int h = col >> 6;
            int d = col & 63;
#pragma unroll
            for (int half = 0; half < 2; half++) {
                int row = rowBase + wm * 32 + mt * 16 + g + half * 8;
                int b = row >> 11;           // / SEQ
                int n = row & (SEQ - 1);
                float2 v;
                v.x = (C[mt][nt][half * 2 + 0] + b0v) * scale;
                v.y = (C[mt][nt][half * 2 + 1] + b1v) * scale;
                __stcs((float2*)&dst[(((size_t)(b * HEADS + h)) * SEQ + n) * HEAD_DIM + d], v);
            }
        }
    }
}

// ============================================================================
// Stage B: flash attention, register softmax (FA2 style).
// CTA = (b, h, 128 q-rows). 8 warps, warp owns 16 rows x all 64 keys/tile.
// 32 key tiles of 64, cp.async double buffered, 2 CTAs/SM.
// S accumulators reused directly as PV A-fragments via V-row permutation.
// ============================================================================
#define KSTR 68                 // both (4g+t) and (8t+g) patterns conflict-free
#define BK 64
#define SQ_F (128 * KSTR)       // 8704 (tf32 words)
#define KT_F (BK * KSTR)        // 4352 floats per K/V tile buffer
#define ATTN_SMEM ((SQ_F + 4 * KT_F) * sizeof(float))   // 104448 B

__global__ void __launch_bounds__(256, 2) attn_kernel(float* __restrict__ out)
{
    extern __shared__ float smem[];
    unsigned* sQ = (unsigned*)smem;
    float* sKb[2] = { smem + SQ_F,            smem + SQ_F + KT_F };
    float* sVb[2] = { smem + SQ_F + 2 * KT_F, smem + SQ_F + 3 * KT_F };

    const int qtile = blockIdx.x;
    const int h = blockIdx.y;
    const int b = blockIdx.z;
    const int bh = b * HEADS + h;
    const float* Qg = g_q + (size_t)bh * SEQ * HEAD_DIM;
    const float* Kg = g_k + (size_t)bh * SEQ * HEAD_DIM;
    const float* Vg = g_v + (size_t)bh * SEQ * HEAD_DIM;

    const int tid = threadIdx.x, warp = tid >> 5, lane = tid & 31;
    const int g = lane >> 2, t = lane & 3;
    const int r0 = warp * 16;              // warp's 16 query rows
    const int qbase = qtile * 128;

    // Load Q tile (128 x 64), tf32-rounded once
#pragma unroll
    for (int i = 0; i < 8; i++) {
        int idx = tid + i * 256;           // 2048 float4
        int r = idx >> 4;
        int c4 = (idx & 15) * 4;
        float4 v = *(const float4*)(Qg + (size_t)(qbase + r) * HEAD_DIM + c4);
        unsigned* p = &sQ[r * KSTR + c4];
        p[0] = f2tf(v.x); p[1] = f2tf(v.y); p[2] = f2tf(v.z); p[3] = f2tf(v.w);
    }

    float O[8][4];
#pragma unroll
    for (int j = 0; j < 8; j++)
#pragma unroll
        for (int k = 0; k < 4; k++) O[j][k] = 0.f;
    float m0 = -1e30f, m1 = -1e30f, l0 = 0.f, l1 = 0.f;

    auto load_tile = [&](int kbase, int bi) {
        unsigned sk = (unsigned)__cvta_generic_to_shared(sKb[bi]);
        unsigned sv = (unsigned)__cvta_generic_to_shared(sVb[bi]);
#pragma unroll
        for (int i = 0; i < 4; i++) {
            int idx = tid + i * 256;       // 1024 chunks each
            int r = idx >> 4;
            int c4 = (idx & 15) * 4;
            CP_ASYNC16(sk + (r * KSTR + c4) * 4, Kg + (size_t)(kbase + r) * HEAD_DIM + c4);
            CP_ASYNC16(sv + (r * KSTR + c4) * 4, Vg + (size_t)(kbase + r) * HEAD_DIM + c4);
        }
    };

    load_tile(0, 0); CP_COMMIT();

    for (int kt = 0; kt < SEQ / BK; kt++) {
        CP_WAIT0();
        __syncthreads();
        if (kt + 1 < SEQ / BK) { load_tile((kt + 1) * BK, (kt + 1) & 1); CP_COMMIT(); }

        const float* Kb = sKb[kt & 1];
        const float* Vb = sVb[kt & 1];

        // ---- S = Q K^T : 16 rows x 64 keys per warp ----
        float Sc[8][4];
#pragma unroll
        for (int j = 0; j < 8; j++)
#pragma unroll
            for (int k = 0; k < 4; k++) Sc[j][k] = 0.f;

#pragma unroll
        for (int kk = 0; kk < HEAD_DIM; kk += 8) {
            unsigned a0 = sQ[(r0 + g)     * KSTR + kk + t];
            unsigned a1 = sQ[(r0 + g + 8) * KSTR + kk + t];
            unsigned a2 = sQ[(r0 + g)     * KSTR + kk + t + 4];
            unsigned a3 = sQ[(r0 + g + 8) * KSTR + kk + t + 4];
            unsigned bf[8][2];
#pragma unroll
            for (int nt = 0; nt < 8; nt++) {
                int n0 = nt * 8;
                bf[nt][0] = f2tf(Kb[(n0 + g) * KSTR + kk + t]);
                bf[nt][1] = f2tf(Kb[(n0 + g) * KSTR + kk + t + 4]);
            }
#pragma unroll
            for (int nt = 0; nt < 8; nt++)
                mma_tf32(Sc[nt], a0, a1, a2, a3, bf[nt][0], bf[nt][1]);
        }

        // ---- Online softmax, fully in registers ----
        // Thread owns rows (r0+g) [c0,c1] and (r0+g+8) [c2,c3]; cols spread over quad.
        float mx0 = -1e30f, mx1 = -1e30f;
#pragma unroll
        for (int nt = 0; nt < 8; nt++) {
            mx0 = fmaxf(mx0, fmaxf(Sc[nt][0], Sc[nt][1]));
            mx1 = fmaxf(mx1, fmaxf(Sc[nt][2], Sc[nt][3]));
        }
        mx0 = fmaxf(mx0, __shfl_xor_sync(0xFFFFFFFFu, mx0, 1));
        mx0 = fmaxf(mx0, __shfl_xor_sync(0xFFFFFFFFu, mx0, 2));
        mx1 = fmaxf(mx1, __shfl_xor_sync(0xFFFFFFFFu, mx1, 1));
        mx1 = fmaxf(mx1, __shfl_xor_sync(0xFFFFFFFFu, mx1, 2));

        float mn0 = fmaxf(m0, mx0), mn1 = fmaxf(m1, mx1);
        float f0 = __expf(m0 - mn0), f1 = __expf(m1 - mn1);

        float s0 = 0.f, s1 = 0.f;
#pragma unroll
        for (int nt = 0; nt < 8; nt++) {
            float p;
            p = __expf(Sc[nt][0] - mn0); s0 += p; Sc[nt][0] = __uint_as_float(f2tf(p));
            p = __expf(Sc[nt][1] - mn0); s0 += p; Sc[nt][1] = __uint_as_float(f2tf(p));
            p = __expf(Sc[nt][2] - mn1); s1 += p; Sc[nt][2] = __uint_as_float(f2tf(p));
            p = __expf(Sc[nt][3] - mn1); s1 += p; Sc[nt][3] = __uint_as_float(f2tf(p));
        }
        s0 += __shfl_xor_sync(0xFFFFFFFFu, s0, 1);
        s0 += __shfl_xor_sync(0xFFFFFFFFu, s0, 2);
        s1 += __shfl_xor_sync(0xFFFFFFFFu, s1, 1);
        s1 += __shfl_xor_sync(0xFFFFFFFFu, s1, 2);

        l0 = l0 * f0 + s0;  l1 = l1 * f1 + s1;
        m0 = mn0;           m1 = mn1;

#pragma unroll
        for (int nt = 0; nt < 8; nt++) {
            O[nt][0] *= f0; O[nt][1] *= f0;
            O[nt][2] *= f1; O[nt][3] *= f1;
        }

        // ---- O += P V : S accumulators ARE the A fragments (V rows permuted) ----
        // A slot t holds P col 2t, slot t+4 holds col 2t+1 -> read V rows 2t, 2t+1.
#pragma unroll
        for (int j = 0; j < 8; j++) {
            unsigned a0 = __float_as_uint(Sc[j][0]);
            unsigned a1 = __float_as_uint(Sc[j][2]);
            unsigned a2 = __float_as_uint(Sc[j][1]);
            unsigned a3 = __float_as_uint(Sc[j][3]);
            unsigned bf[8][2];
#pragma unroll
            for (int nt = 0; nt < 8; nt++) {
                int n0 = nt * 8;
                bf[nt][0] = f2tf(Vb[(j * 8 + 2 * t)     * KSTR + n0 + g]);
                bf[nt][1] = f2tf(Vb[(j * 8 + 2 * t + 1) * KSTR + n0 + g]);
            }
#pragma unroll
            for (int nt = 0; nt < 8; nt++)
                mma_tf32(O[nt], a0, a1, a2, a3, bf[nt][0], bf[nt][1]);
        }
    }

    // ---- Epilogue: O /= l, write [B, N, E] (float2 stores) ----
    float li0 = 1.f / l0, li1 = 1.f / l1;
    int n_lo = qbase + r0 + g;
    int n_hi = n_lo + 8;
    float* out_lo = out + ((size_t)b * SEQ + n_lo) * EMBED + h * HEAD_DIM;
    float* out_hi = out + ((size_t)b * SEQ + n_hi) * EMBED + h * HEAD_DIM;
#pragma unroll
    for (int nt = 0; nt < 8; nt++) {
        int d = nt * 8 + 2 * t;
        float2 v0; v0.x = O[nt][0] * li0; v0.y = O[nt][1] * li0;
        float2 v1; v1.x = O[nt][2] * li1; v1.y = O[nt][3] * li1;
        *(float2*)&out_lo[d] = v0;
        *(float2*)&out_hi[d] = v1;
    }
}

extern "C" void kernel_launch(void* const* d_in, const int* in_sizes, int n_in,
                              void* d_out, int out_size)
{
    const float* query = (const float*)d_in[0];
    const float* key   = (const float*)d_in[1];
    const float* value = (const float*)d_in[2];
    const float* Wq = (const float*)d_in[3];
    const float* bq = (const float*)d_in[4];
    const float* Wk = (const float*)d_in[5];
    const float* bk = (const float*)d_in[6];
    const float* Wv = (const float*)d_in[7];
    const float* bv = (const float*)d_in[8];
    float* out = (float*)d_out;

    (void)in_sizes; (void)n_in; (void)out_size;

    cudaFuncSetAttribute(qkv_gemm_kernel, cudaFuncAttributeMaxDynamicSharedMemorySize,
                         (int)QKV_SMEM);
    cudaFuncSetAttribute(attn_kernel, cudaFuncAttributeMaxDynamicSharedMemorySize,
                         (int)ATTN_SMEM);

    // Stage A: QKV projections (z = 0/1/2 -> q/k/v)
    dim3 ggrid(EMBED / 128, MTOT / 128, 3);
    qkv_gemm_kernel<<<ggrid, 256, QKV_SMEM>>>(query, key, value, Wq, bq, Wk, bk, Wv, bv);

    // Stage B: flash attention
    dim3 agrid(SEQ / 128, HEADS, BATCH);
    attn_kernel<<<agrid, 256, ATTN_SMEM>>>(out);
}

// round 10
// speedup vs baseline: 1.5369x; 1.0431x over previous
#include <cuda_runtime.h>

#define EMBED 1024
#define HEADS 16
#define HEAD_DIM 64
#define BATCH 2
#define SEQ 2048
#define MTOT (BATCH * SEQ)   // 4096

// Scratch for projected Q/K/V in [B,H,N,Dh] layout, stored as tf32-rounded
// bit patterns (cvt.rna applied ONCE in the GEMM epilogue). Q pre-scaled by 1/8.
__device__ float g_q[BATCH * HEADS * SEQ * HEAD_DIM];
__device__ float g_k[BATCH * HEADS * SEQ * HEAD_DIM];
__device__ float g_v[BATCH * HEADS * SEQ * HEAD_DIM];

__device__ __forceinline__ unsigned f2tf(float x) {
    unsigned r;
    asm("cvt.rna.tf32.f32 %0, %1;" : "=r"(r) : "f"(x));
    return r;
}

__device__ __forceinline__ void mma_tf32(float c[4],
                                         unsigned a0, unsigned a1, unsigned a2, unsigned a3,
                                         unsigned b0, unsigned b1) {
    asm volatile(
        "mma.sync.aligned.m16n8k8.row.col.f32.tf32.tf32.f32 "
        "{%0,%1,%2,%3},{%4,%5,%6,%7},{%8,%9},{%0,%1,%2,%3};"
        : "+f"(c[0]), "+f"(c[1]), "+f"(c[2]), "+f"(c[3])
        : "r"(a0), "r"(a1), "r"(a2), "r"(a3), "r"(b0), "r"(b1));
}

#define CP_ASYNC16(dst_u32, src_ptr) \
    asm volatile("cp.async.ca.shared.global [%0], [%1], 16;" :: "r"(dst_u32), "l"(src_ptr))
#define CP_COMMIT() asm volatile("cp.async.commit_group;")
#define CP_WAIT0()  asm volatile("cp.async.wait_group 0;")

// ============================================================================
// Stage A: QKV projection.  Y[m,o] = sum_e X[m,e] * W[o,e] + b[o]
// 128x128 tile, K-tile 32, cp.async double buffered, 2 CTAs/SM.
// Epilogue stores tf32-rounded bit patterns (consumed raw by attention).
// ============================================================================
#define ASTR 36                    // (4g+t) bank pattern conflict-free
#define QKV_TILE (128 * ASTR)      // floats per tile buffer
#define QKV_SMEM (4 * QKV_TILE * sizeof(float))   // 73728 B

__global__ void __launch_bounds__(256, 2) qkv_gemm_kernel(
    const float* __restrict__ Xq, const float* __restrict__ Xk, const float* __restrict__ Xv,
    const float* __restrict__ Wq, const float* __restrict__ bq,
    const float* __restrict__ Wk, const float* __restrict__ bk,
    const float* __restrict__ Wv, const float* __restrict__ bv)
{
    extern __shared__ float smem[];
    float* sAb[2] = { smem,                smem + QKV_TILE };
    float* sBb[2] = { smem + 2 * QKV_TILE, smem + 3 * QKV_TILE };

    const int z = blockIdx.z;
    const float* X    = (z == 0) ? Xq : (z == 1) ? Xk : Xv;
    const float* W    = (z == 0) ? Wq : (z == 1) ? Wk : Wv;
    const float* bias = (z == 0) ? bq : (z == 1) ? bk : bv;
    float* dst        = (z == 0) ? g_q : (z == 1) ? g_k : g_v;
    const float scale = (z == 0) ? 0.125f : 1.0f;   // HEAD_DIM^-0.5 = 1/8

    const int rowBase = blockIdx.y * 128;
    const int colBase = blockIdx.x * 128;
    const int tid  = threadIdx.x;
    const int warp = tid >> 5, lane = tid & 31;
    const int wm = warp >> 1, wn = warp & 1;
    const int g = lane >> 2, t = lane & 3;

    float C[2][8][4];
#pragma unroll
    for (int i = 0; i < 2; i++)
#pragma unroll
        for (int j = 0; j < 8; j++)
#pragma unroll
            for (int k = 0; k < 4; k++) C[i][j][k] = 0.f;

    auto load_tile = [&](int k0, int bi) {
        unsigned sa = (unsigned)__cvta_generic_to_shared(sAb[bi]);
        unsigned sb = (unsigned)__cvta_generic_to_shared(sBb[bi]);
#pragma unroll
        for (int i = 0; i < 4; i++) {
            int idx = tid + i * 256;
            int r = idx >> 3;
            int c4 = (idx & 7) * 4;
            CP_ASYNC16(sa + (r * ASTR + c4) * 4, X + (size_t)(rowBase + r) * EMBED + k0 + c4);
            CP_ASYNC16(sb + (r * ASTR + c4) * 4, W + (size_t)(colBase + r) * EMBED + k0 + c4);
        }
    };

    load_tile(0, 0); CP_COMMIT();

    for (int kt = 0; kt < EMBED / 32; kt++) {
        CP_WAIT0();
        __syncthreads();
        if (kt + 1 < EMBED / 32) { load_tile((kt + 1) * 32, (kt + 1) & 1); CP_COMMIT(); }

        const float* A = sAb[kt & 1];
        const float* B = sBb[kt & 1];

#pragma unroll
        for (int kk = 0; kk < 32; kk += 8) {
            unsigned a[2][4];
#pragma unroll
            for (int mt = 0; mt < 2; mt++) {
                int r0 = wm * 32 + mt * 16;
                a[mt][0] = f2tf(A[(r0 + g)     * ASTR + kk + t]);
                a[mt][1] = f2tf(A[(r0 + g + 8) * ASTR + kk + t]);
                a[mt][2] = f2tf(A[(r0 + g)     * ASTR + kk + t + 4]);
                a[mt][3] = f2tf(A[(r0 + g + 8) * ASTR + kk + t + 4]);
            }
            unsigned bf[8][2];
#pragma unroll
            for (int nt = 0; nt < 8; nt++) {
                int n0 = wn * 64 + nt * 8;
                bf[nt][0] = f2tf(B[(n0 + g) * ASTR + kk + t]);
                bf[nt][1] = f2tf(B[(n0 + g) * ASTR + kk + t + 4]);
            }
#pragma unroll
            for (int nt = 0; nt < 8; nt++) {
                mma_tf32(C[0][nt], a[0][0], a[0][1], a[0][2], a[0][3], bf[nt][0], bf[nt][1]);
                mma_tf32(C[1][nt], a[1][0], a[1][1], a[1][2], a[1][3], bf[nt][0], bf[nt][1]);
            }
        }
    }

    // Epilogue: bias, scale, tf32-round ONCE, scatter into [B,H,N,Dh] (streaming)
#pragma unroll
    for (int mt = 0; mt < 2; mt++) {
#pragma unroll
        for (int nt = 0; nt < 8; nt++) {
            int col = colBase + wn * 64 + nt * 8 + 2 * t;
            float b0v = bias[col], b1v = bias[col + 1];
            int h = col >> 6;
            int d = col & 63;
#pragma unroll
            for (int half = 0; half < 2; half++) {
                int row = rowBase + wm * 32 + mt * 16 + g + half * 8;
                int b = row >> 11;           // / SEQ
                int n = row & (SEQ - 1);
                float2 v;
                v.x = __uint_as_float(f2tf((C[mt][nt][half * 2 + 0] + b0v) * scale));
                v.y = __uint_as_float(f2tf((C[mt][nt][half * 2 + 1] + b1v) * scale));
                __stcs((float2*)&dst[(((size_t)(b * HEADS + h)) * SEQ + n) * HEAD_DIM + d], v);
            }
        }
    }
}

// ============================================================================
// Stage B: flash attention, register softmax (FA2 style).
// CTA = (b, h, 128 q-rows). 8 warps, warp owns 16 rows x all 64 keys/tile.
// 32 key tiles of 64, cp.async double buffered, 2 CTAs/SM.
// Q/K/V already tf32 in gmem -> ZERO conversions on fragment loads.
// S accumulators reused directly as PV A-fragments via V-row permutation.
// ============================================================================
#define KSTR 68                 // both (4g+t) and (8t+g) patterns conflict-free
#define BK 64
#define SQ_F (128 * KSTR)       // 8704 (tf32 words)
#define KT_F (BK * KSTR)        // 4352 floats per K/V tile buffer
#define ATTN_SMEM ((SQ_F + 4 * KT_F) * sizeof(float))   // 104448 B

__global__ void __launch_bounds__(256, 2) attn_kernel(float* __restrict__ out)
{
    extern __shared__ float smem[];
    unsigned* sQ = (unsigned*)smem;
    float* sKb[2] = { smem + SQ_F,            smem + SQ_F + KT_F };
    float* sVb[2] = { smem + SQ_F + 2 * KT_F, smem + SQ_F + 3 * KT_F };

    const int qtile = blockIdx.x;
    const int h = blockIdx.y;
    const int b = blockIdx.z;
    const int bh = b * HEADS + h;
    const float* Qg = g_q + (size_t)bh * SEQ * HEAD_DIM;
    const float* Kg = g_k + (size_t)bh * SEQ * HEAD_DIM;
    const float* Vg = g_v + (size_t)bh * SEQ * HEAD_DIM;

    const int tid = threadIdx.x, warp = tid >> 5, lane = tid & 31;
    const int g = lane >> 2, t = lane & 3;
    const int r0 = warp * 16;              // warp's 16 query rows
    const int qbase = qtile * 128;

    // Q tile (128 x 64) via cp.async — already tf32 bit patterns
    {
        unsigned sq = (unsigned)__cvta_generic_to_shared(sQ);
#pragma unroll
        for (int i = 0; i < 8; i++) {
            int idx = tid + i * 256;           // 2048 16B chunks
            int r = idx >> 4;
            int c4 = (idx & 15) * 4;
            CP_ASYNC16(sq + (r * KSTR + c4) * 4, Qg + (size_t)(qbase + r) * HEAD_DIM + c4);
        }
    }

    float O[8][4];
#pragma unroll
    for (int j = 0; j < 8; j++)
#pragma unroll
        for (int k = 0; k < 4; k++) O[j][k] = 0.f;
    float m0 = -1e30f, m1 = -1e30f, l0 = 0.f, l1 = 0.f;

    auto load_tile = [&](int kbase, int bi) {
        unsigned sk = (unsigned)__cvta_generic_to_shared(sKb[bi]);
        unsigned sv = (unsigned)__cvta_generic_to_shared(sVb[bi]);
#pragma unroll
        for (int i = 0; i < 4; i++) {
            int idx = tid + i * 256;       // 1024 chunks each
            int r = idx >> 4;
            int c4 = (idx & 15) * 4;
            CP_ASYNC16(sk + (r * KSTR + c4) * 4, Kg + (size_t)(kbase + r) * HEAD_DIM + c4);
            CP_ASYNC16(sv + (r * KSTR + c4) * 4, Vg + (size_t)(kbase + r) * HEAD_DIM + c4);
        }
    };

    load_tile(0, 0); CP_COMMIT();          // Q chunks ride in the same group

    for (int kt = 0; kt < SEQ / BK; kt++) {
        CP_WAIT0();
        __syncthreads();
        if (kt + 1 < SEQ / BK) { load_tile((kt + 1) * BK, (kt + 1) & 1); CP_COMMIT(); }

        const unsigned* Kb = (const unsigned*)sKb[kt & 1];
        const unsigned* Vb = (const unsigned*)sVb[kt & 1];

        // ---- S = Q K^T : 16 rows x 64 keys per warp (raw tf32 loads) ----
        float Sc[8][4];
#pragma unroll
        for (int j = 0; j < 8; j++)
#pragma unroll
            for (int k = 0; k < 4; k++) Sc[j][k] = 0.f;

#pragma unroll
        for (int kk = 0; kk < HEAD_DIM; kk += 8) {
            unsigned a0 = sQ[(r0 + g)     * KSTR + kk + t];
            unsigned a1 = sQ[(r0 + g + 8) * KSTR + kk + t];
            unsigned a2 = sQ[(r0 + g)     * KSTR + kk + t + 4];
            unsigned a3 = sQ[(r0 + g + 8) * KSTR + kk + t + 4];
#pragma unroll
            for (int nt = 0; nt < 8; nt++) {
                int n0 = nt * 8;
                unsigned b0 = Kb[(n0 + g) * KSTR + kk + t];
                unsigned b1 = Kb[(n0 + g) * KSTR + kk + t + 4];
                mma_tf32(Sc[nt], a0, a1, a2, a3, b0, b1);
            }
        }

        // ---- Online softmax, fully in registers ----
        float mx0 = -1e30f, mx1 = -1e30f;
#pragma unroll
        for (int nt = 0; nt < 8; nt++) {
            mx0 = fmaxf(mx0, fmaxf(Sc[nt][0], Sc[nt][1]));
            mx1 = fmaxf(mx1, fmaxf(Sc[nt][2], Sc[nt][3]));
        }
        mx0 = fmaxf(mx0, __shfl_xor_sync(0xFFFFFFFFu, mx0, 1));
        mx0 = fmaxf(mx0, __shfl_xor_sync(0xFFFFFFFFu, mx0, 2));
        mx1 = fmaxf(mx1, __shfl_xor_sync(0xFFFFFFFFu, mx1, 1));
        mx1 = fmaxf(mx1, __shfl_xor_sync(0xFFFFFFFFu, mx1, 2));

        float mn0 = fmaxf(m0, mx0), mn1 = fmaxf(m1, mx1);
        float f0 = __expf(m0 - mn0), f1 = __expf(m1 - mn1);

        float s0 = 0.f, s1 = 0.f;
#pragma unroll
        for (int nt = 0; nt < 8; nt++) {
            float p;
            p = __expf(Sc[nt][0] - mn0); s0 += p; Sc[nt][0] = __uint_as_float(f2tf(p));
            p = __expf(Sc[nt][1] - mn0); s0 += p; Sc[nt][1] = __uint_as_float(f2tf(p));
            p = __expf(Sc[nt][2] - mn1); s1 += p; Sc[nt][2] = __uint_as_float(f2tf(p));
            p = __expf(Sc[nt][3] - mn1); s1 += p; Sc[nt][3] = __uint_as_float(f2tf(p));
        }
        s0 += __shfl_xor_sync(0xFFFFFFFFu, s0, 1);
        s0 += __shfl_xor_sync(0xFFFFFFFFu, s0, 2);
        s1 += __shfl_xor_sync(0xFFFFFFFFu, s1, 1);
        s1 += __shfl_xor_sync(0xFFFFFFFFu, s1, 2);

        l0 = l0 * f0 + s0;  l1 = l1 * f1 + s1;
        m0 = mn0;           m1 = mn1;

#pragma unroll
        for (int nt = 0; nt < 8; nt++) {
            O[nt][0] *= f0; O[nt][1] *= f0;
            O[nt][2] *= f1; O[nt][3] *= f1;
        }

        // ---- O += P V : S accumulators ARE the A fragments (V rows permuted) ----
#pragma unroll
        for (int j = 0; j < 8; j++) {
            unsigned a0 = __float_as_uint(Sc[j][0]);
            unsigned a1 = __float_as_uint(Sc[j][2]);
            unsigned a2 = __float_as_uint(Sc[j][1]);
            unsigned a3 = __float_as_uint(Sc[j][3]);
#pragma unroll
            for (int nt = 0; nt < 8; nt++) {
                int n0 = nt * 8;
                unsigned b0 = Vb[(j * 8 + 2 * t)     * KSTR + n0 + g];
                unsigned b1 = Vb[(j * 8 + 2 * t + 1) * KSTR + n0 + g];
                mma_tf32(O[nt], a0, a1, a2, a3, b0, b1);
            }
        }
    }

    // ---- Epilogue: O /= l, write [B, N, E] (float2 stores) ----
    float li0 = 1.f / l0, li1 = 1.f / l1;
    int n_lo = qbase + r0 + g;
    int n_hi = n_lo + 8;
    float* out_lo = out + ((size_t)b * SEQ + n_lo) * EMBED + h * HEAD_DIM;
    float* out_hi = out + ((size_t)b * SEQ + n_hi) * EMBED + h * HEAD_DIM;
#pragma unroll
    for (int nt = 0; nt < 8; nt++) {
        int d = nt * 8 + 2 * t;
        float2 v0; v0.x = O[nt][0] * li0; v0.y = O[nt][1] * li0;
        float2 v1; v1.x = O[nt][2] * li1; v1.y = O[nt][3] * li1;
        *(float2*)&out_lo[d] = v0;
        *(float2*)&out_hi[d] = v1;
    }
}

extern "C" void kernel_launch(void* const* d_in, const int* in_sizes, int n_in,
                              void* d_out, int out_size)
{
    const float* query = (const float*)d_in[0];
    const float* key   = (const float*)d_in[1];
    const float* value = (const float*)d_in[2];
    const float* Wq = (const float*)d_in[3];
    const float* bq = (const float*)d_in[4];
    const float* Wk = (const float*)d_in[5];
    const float* bk = (const float*)d_in[6];
    const float* Wv = (const float*)d_in[7];
    const float* bv = (const float*)d_in[8];
    float* out = (float*)d_out;

    (void)in_sizes; (void)n_in; (void)out_size;

    cudaFuncSetAttribute(qkv_gemm_kernel, cudaFuncAttributeMaxDynamicSharedMemorySize,
                         (int)QKV_SMEM);
    cudaFuncSetAttribute(attn_kernel, cudaFuncAttributeMaxDynamicSharedMemorySize,
                         (int)ATTN_SMEM);

    // Stage A: QKV projections (z = 0/1/2 -> q/k/v)
    dim3 ggrid(EMBED / 128, MTOT / 128, 3);
    qkv_gemm_kernel<<<ggrid, 256, QKV_SMEM>>>(query, key, value, Wq, bq, Wk, bk, Wv, bv);

    // Stage B: flash attention
    dim3 agrid(SEQ / 128, HEADS, BATCH);
    attn_kernel<<<agrid, 256, ATTN_SMEM>>>(out);
}

// round 12
// speedup vs baseline: 1.9321x; 1.2571x over previous
#include <cuda_runtime.h>

#define EMBED 1024
#define HEADS 16
#define HEAD_DIM 64
#define BATCH 2
#define SEQ 2048
#define MTOT (BATCH * SEQ)   // 4096

// Projected Q/K in [B,H,N,Dh]; V transposed as VT in [B,H,Dh,N].
// All stored as tf32-rounded bit patterns. Q pre-scaled by Dh^-0.5.
__device__ float g_q [BATCH * HEADS * SEQ * HEAD_DIM];
__device__ float g_k [BATCH * HEADS * SEQ * HEAD_DIM];
__device__ float g_vt[BATCH * HEADS * HEAD_DIM * SEQ];
// tf32-pre-rounded copies of inputs (prepass) so GEMM smem holds raw tf32.
__device__ float g_xr[3 * MTOT * EMBED];
__device__ float g_wr[3 * EMBED * EMBED];

__device__ __forceinline__ unsigned f2tf(float x) {
    unsigned r;
    asm("cvt.rna.tf32.f32 %0, %1;" : "=r"(r) : "f"(x));
    return r;
}

__device__ __forceinline__ void mma_tf32(float c[4],
                                         unsigned a0, unsigned a1, unsigned a2, unsigned a3,
                                         unsigned b0, unsigned b1) {
    asm volatile(
        "mma.sync.aligned.m16n8k8.row.col.f32.tf32.tf32.f32 "
        "{%0,%1,%2,%3},{%4,%5,%6,%7},{%8,%9},{%0,%1,%2,%3};"
        : "+f"(c[0]), "+f"(c[1]), "+f"(c[2]), "+f"(c[3])
        : "r"(a0), "r"(a1), "r"(a2), "r"(a3), "r"(b0), "r"(b1));
}

__device__ __forceinline__ void ldsm4(unsigned& r0, unsigned& r1, unsigned& r2, unsigned& r3,
                                      unsigned addr) {
    asm volatile("ldmatrix.sync.aligned.m8n8.x4.shared.b16 {%0,%1,%2,%3}, [%4];"
                 : "=r"(r0), "=r"(r1), "=r"(r2), "=r"(r3) : "r"(addr));
}

#define CP_ASYNC16(dst_u32, src_ptr) \
    asm volatile("cp.async.ca.shared.global [%0], [%1], 16;" :: "r"(dst_u32), "l"(src_ptr))
#define CP_COMMIT() asm volatile("cp.async.commit_group;")
#define CP_WAIT0()  asm volatile("cp.async.wait_group 0;")

// ============================================================================
// Stage 0: prepass — tf32-round X and W once (bit-identical to rounding at use).
// ============================================================================
__global__ void round_kernel(const float4* __restrict__ src, float4* __restrict__ dst, int n4)
{
    int i = blockIdx.x * blockDim.x + threadIdx.x;
    int stride = gridDim.x * blockDim.x;
    for (; i < n4; i += stride) {
        float4 v = src[i];
        v.x = __uint_as_float(f2tf(v.x));
        v.y = __uint_as_float(f2tf(v.y));
        v.z = __uint_as_float(f2tf(v.z));
        v.w = __uint_as_float(f2tf(v.w));
        dst[i] = v;
    }
}

// ============================================================================
// Stage A: QKV projection via pure-LDSM tf32 MMA (smem already tf32).
// 128x128 tile, K-tile 32, cp.async double buffered, 2 CTAs/SM.
// z=0 -> g_q (scaled 1/8), z=1 -> g_k, z=2 -> g_vt (transposed scatter).
// ============================================================================
#define ASTR 36
#define QKV_TILE (128 * ASTR)
#define QKV_SMEM (4 * QKV_TILE * sizeof(float))   // 73728 B

__global__ void __launch_bounds__(256, 2) qkv_gemm_kernel(
    const float* __restrict__ bq, const float* __restrict__ bk, const float* __restrict__ bv)
{
    extern __shared__ float smem[];
    float* sAb[2] = { smem,                smem + QKV_TILE };
    float* sBb[2] = { smem + 2 * QKV_TILE, smem + 3 * QKV_TILE };

    const int z = blockIdx.z;
    const float* X    = g_xr + (size_t)z * MTOT * EMBED;
    const float* W    = g_wr + (size_t)z * EMBED * EMBED;
    const float* bias = (z == 0) ? bq : (z == 1) ? bk : bv;
    const float scale = (z == 0) ? 0.125f : 1.0f;

    const int rowBase = blockIdx.y * 128;
    const int colBase = blockIdx.x * 128;
    const int tid  = threadIdx.x;
    const int warp = tid >> 5, lane = tid & 31;
    const int wm = warp >> 1, wn = warp & 1;
    const int g = lane >> 2, t = lane & 3;
    const int lr = lane & 7, mi = lane >> 3;
    // ldmatrix per-lane row/col offsets (A pattern and B pattern)
    const int a_row = lr + ((mi & 1) << 3), a_col = (mi >> 1) << 2;
    const int b_row = lr + ((mi >> 1) << 3), b_col = (mi & 1) << 2;

    const unsigned aB[2] = { (unsigned)__cvta_generic_to_shared(sAb[0]),
                             (unsigned)__cvta_generic_to_shared(sAb[1]) };
    const unsigned bB[2] = { (unsigned)__cvta_generic_to_shared(sBb[0]),
                             (unsigned)__cvta_generic_to_shared(sBb[1]) };

    float C[2][8][4];
#pragma unroll
    for (int i = 0; i < 2; i++)
#pragma unroll
        for (int j = 0; j < 8; j++)
#pragma unroll
            for (int k = 0; k < 4; k++) C[i][j][k] = 0.f;

    auto load_tile = [&](int k0, int bi) {
        unsigned sa = aB[bi], sb = bB[bi];
#pragma unroll
        for (int i = 0; i < 4; i++) {
            int idx = tid + i * 256;
            int r = idx >> 3;
            int c4 = (idx & 7) * 4;
            CP_ASYNC16(sa + (r * ASTR + c4) * 4, X + (size_t)(rowBase + r) * EMBED + k0 + c4);
            CP_ASYNC16(sb + (r * ASTR + c4) * 4, W + (size_t)(colBase + r) * EMBED + k0 + c4);
        }
    };

    load_tile(0, 0); CP_COMMIT();

    for (int kt = 0; kt < EMBED / 32; kt++) {
        CP_WAIT0();
        __syncthreads();
        if (kt + 1 < EMBED / 32) { load_tile((kt + 1) * 32, (kt + 1) & 1); CP_COMMIT(); }

        const unsigned aBase = aB[kt & 1];
        const unsigned bBase = bB[kt & 1];

#pragma unroll
        for (int kk = 0; kk < 32; kk += 8) {
            unsigned a[2][4];
#pragma unroll
            for (int mt = 0; mt < 2; mt++)
                ldsm4(a[mt][0], a[mt][1], a[mt][2], a[mt][3],
                      aBase + (((wm * 32 + mt * 16) + a_row) * ASTR + kk + a_col) * 4);
#pragma unroll
            for (int np = 0; np < 4; np++) {
                unsigned b0A, b1A, b0B, b1B;
                ldsm4(b0A, b1A, b0B, b1B,
                      bBase + (((wn * 64 + np * 16) + b_row) * ASTR + kk + b_col) * 4);
                mma_tf32(C[0][2 * np],     a[0][0], a[0][1], a[0][2], a[0][3], b0A, b1A);
                mma_tf32(C[1][2 * np],     a[1][0], a[1][1], a[1][2], a[1][3], b0A, b1A);
                mma_tf32(C[0][2 * np + 1], a[0][0], a[0][1], a[0][2], a[0][3], b0B, b1B);
                mma_tf32(C[1][2 * np + 1], a[1][0], a[1][1], a[1][2], a[1][3], b0B, b1B);
            }
        }
    }

    // Epilogue: bias, scale, tf32-round ONCE, scatter (Q/K normal, V transposed)
#pragma unroll
    for (int mt = 0; mt < 2; mt++) {
#pragma unroll
        for (int nt = 0; nt < 8; nt++) {
            int col = colBase + wn * 64 + nt * 8 + 2 * t;
            float b0v = bias[col], b1v = bias[col + 1];
            int h = col >> 6;
            int d = col & 63;
#pragma unroll
            for (int half = 0; half < 2; half++) {
                int row = rowBase + wm * 32 + mt * 16 + g + half * 8;
                int b = row >> 11;
                int n = row & (SEQ - 1);
                int bh = b * HEADS + h;
                float v0 = __uint_as_float(f2tf((C[mt][nt][half * 2 + 0] + b0v) * scale));
                float v1 = __uint_as_float(f2tf((C[mt][nt][half * 2 + 1] + b1v) * scale));
                if (z < 2) {
                    float* dst = (z == 0) ? g_q : g_k;
                    float2 v; v.x = v0; v.y = v1;
                    __stcs((float2*)&dst[(((size_t)bh) * SEQ + n) * HEAD_DIM + d], v);
                } else {
                    // VT[bh][d][n]
                    __stcs(&g_vt[(((size_t)bh) * HEAD_DIM + d)     * SEQ + n], v0);
                    __stcs(&g_vt[(((size_t)bh) * HEAD_DIM + d + 1) * SEQ + n], v1);
                }
            }
        }
    }
}

// ============================================================================
// Stage B: flash attention, register softmax, LDSM fragments, VT LDS.64.
// CTA = (b, h, 128 q-rows). 8 warps x 16 rows. 32 key tiles of 64.
// cp.async double buffered, 2 CTAs/SM.
// ============================================================================
#define KSTR 68                 // 68%32==4: LDSM rows on distinct bank quads
#define VTSTR 72                // 72%32==8: (8g+2t) LDS.64 pattern conflict-free
#define BK 64
#define SQ_F (128 * KSTR)       // 8704
#define KT_F (BK * KSTR)        // 4352
#define VT_F (HEAD_DIM * VTSTR) // 4608
#define SK0_OFF SQ_F
#define SK1_OFF (SQ_F + KT_F)
#define SV0_OFF (SQ_F + 2 * KT_F)
#define SV1_OFF (SQ_F + 2 * KT_F + VT_F)
#define ATTN_SMEM ((SQ_F + 2 * KT_F + 2 * VT_F) * sizeof(float))   // 106496 B

__global__ void __launch_bounds__(256, 2) attn_kernel(float* __restrict__ out)
{
    extern __shared__ float smem[];

    const int qtile = blockIdx.x;
    const int h = blockIdx.y;
    const int b = blockIdx.z;
    const int bh = b * HEADS + h;
    const float* Qg  = g_q  + (size_t)bh * SEQ * HEAD_DIM;
    const float* Kg  = g_k  + (size_t)bh * SEQ * HEAD_DIM;
    const float* VTg = g_vt + (size_t)bh * HEAD_DIM * SEQ;

    const int tid = threadIdx.x, warp = tid >> 5, lane = tid & 31;
    const int g = lane >> 2, t = lane & 3;
    const int lr = lane & 7, mi = lane >> 3;
    const int a_row = lr + ((mi & 1) << 3), a_col = (mi >> 1) << 2;
    const int b_row = lr + ((mi >> 1) << 3), b_col = (mi & 1) << 2;
    const int r0 = warp * 16;
    const int qbase = qtile * 128;

    const unsigned sqB = (unsigned)__cvta_generic_to_shared(smem);
    const unsigned skB[2] = { (unsigned)__cvta_generic_to_shared(smem + SK0_OFF),
                              (unsigned)__cvta_generic_to_shared(smem + SK1_OFF) };
    const float* sV[2] = { smem + SV0_OFF, smem + SV1_OFF };
    const unsigned svB[2] = { (unsigned)__cvta_generic_to_shared(smem + SV0_OFF),
                              (unsigned)__cvta_generic_to_shared(smem + SV1_OFF) };

    // Q tile (128 x 64) via cp.async (tf32 bits)
#pragma unroll
    for (int i = 0; i < 8; i++) {
        int idx = tid + i * 256;
        int r = idx >> 4;
        int c4 = (idx & 15) * 4;
        CP_ASYNC16(sqB + (r * KSTR + c4) * 4, Qg + (size_t)(qbase + r) * HEAD_DIM + c4);
    }

    float O[8][4];
#pragma unroll
    for (int j = 0; j < 8; j++)
#pragma unroll
        for (int k = 0; k < 4; k++) O[j][k] = 0.f;
    float m0 = -1e30f, m1 = -1e30f, l0 = 0.f, l1 = 0.f;

    auto load_tile = [&](int kbase, int bi) {
        unsigned sk = skB[bi], sv = svB[bi];
#pragma unroll
        for (int i = 0; i < 4; i++) {
            int idx = tid + i * 256;
            int r = idx >> 4;                 // K: key row / VT: d row
            int c4 = (idx & 15) * 4;
            CP_ASYNC16(sk + (r * KSTR  + c4) * 4, Kg  + (size_t)(kbase + r) * HEAD_DIM + c4);
            CP_ASYNC16(sv + (r * VTSTR + c4) * 4, VTg + (size_t)r * SEQ + kbase + c4);
        }
    };

    load_tile(0, 0); CP_COMMIT();

    for (int kt = 0; kt < SEQ / BK; kt++) {
        CP_WAIT0();
        __syncthreads();
        if (kt + 1 < SEQ / BK) { load_tile((kt + 1) * BK, (kt + 1) & 1); CP_COMMIT(); }

        const unsigned kBase = skB[kt & 1];
        const float* Vb = sV[kt & 1];

        // ---- S = Q K^T : LDSM fragments ----
        float Sc[8][4];
#pragma unroll
        for (int j = 0; j < 8; j++)
#pragma unroll
            for (int k = 0; k < 4; k++) Sc[j][k] = 0.f;

#pragma unroll
        for (int kk = 0; kk < HEAD_DIM; kk += 8) {
            unsigned a0, a1, a2, a3;
            ldsm4(a0, a1, a2, a3, sqB + ((r0 + a_row) * KSTR + kk + a_col) * 4);
#pragma unroll
            for (int np = 0; np < 4; np++) {
                unsigned b0A, b1A, b0B, b1B;
                ldsm4(b0A, b1A, b0B, b1B,
                      kBase + ((np * 16 + b_row) * KSTR + kk + b_col) * 4);
                mma_tf32(Sc[2 * np],     a0, a1, a2, a3, b0A, b1A);
                mma_tf32(Sc[2 * np + 1], a0, a1, a2, a3, b0B, b1B);
            }
        }

        // ---- Online softmax, fully in registers ----
        float mx0 = -1e30f, mx1 = -1e30f;
#pragma unroll
        for (int nt = 0; nt < 8; nt++) {
            mx0 = fmaxf(mx0, fmaxf(Sc[nt][0], Sc[nt][1]));
            mx1 = fmaxf(mx1, fmaxf(Sc[nt][2], Sc[nt][3]));
        }
        mx0 = fmaxf(mx0, __shfl_xor_sync(0xFFFFFFFFu, mx0, 1));
        mx0 = fmaxf(mx0, __shfl_xor_sync(0xFFFFFFFFu, mx0, 2));
        mx1 = fmaxf(mx1, __shfl_xor_sync(0xFFFFFFFFu, mx1, 1));
        mx1 = fmaxf(mx1, __shfl_xor_sync(0xFFFFFFFFu, mx1, 2));

        float mn0 = fmaxf(m0, mx0), mn1 = fmaxf(m1, mx1);
        float f0 = __expf(m0 - mn0), f1 = __expf(m1 - mn1);

        float s0 = 0.f, s1 = 0.f;
#pragma unroll
        for (int nt = 0; nt < 8; nt++) {
            float p;
            p = __expf(Sc[nt][0] - mn0); s0 += p; Sc[nt][0] = __uint_as_float(f2tf(p));
            p = __expf(Sc[nt][1] - mn0); s0 += p; Sc[nt][1] = __uint_as_float(f2tf(p));
            p = __expf(Sc[nt][2] - mn1); s1 += p; Sc[nt][2] = __uint_as_float(f2tf(p));
            p = __expf(Sc[nt][3] - mn1); s1 += p; Sc[nt][3] = __uint_as_float(f2tf(p));
        }
        s0 += __shfl_xor_sync(0xFFFFFFFFu, s0, 1);
        s0 += __shfl_xor_sync(0xFFFFFFFFu, s0, 2);
        s1 += __shfl_xor_sync(0xFFFFFFFFu, s1, 1);
        s1 += __shfl_xor_sync(0xFFFFFFFFu, s1, 2);

        l0 = l0 * f0 + s0;  l1 = l1 * f1 + s1;
        m0 = mn0;           m1 = mn1;

#pragma unroll
        for (int nt = 0; nt < 8; nt++) {
            O[nt][0] *= f0; O[nt][1] *= f0;
            O[nt][2] *= f1; O[nt][3] *= f1;
        }

        // ---- O += P V : Sc as A-frags (permuted), VT rows give LDS.64 B-frags ----
#pragma unroll
        for (int j = 0; j < 8; j++) {
            unsigned a0 = __float_as_uint(Sc[j][0]);
            unsigned a1 = __float_as_uint(Sc[j][2]);
            unsigned a2 = __float_as_uint(Sc[j][1]);
            unsigned a3 = __float_as_uint(Sc[j][3]);
#pragma unroll
            for (int nt = 0; nt < 8; nt++) {
                float2 v = *(const float2*)&Vb[(nt * 8 + g) * VTSTR + j * 8 + 2 * t];
                mma_tf32(O[nt], a0, a1, a2, a3,
                         __float_as_uint(v.x), __float_as_uint(v.y));
            }
        }
    }

    // ---- Epilogue: O /= l, write [B, N, E] (float2 stores) ----
    float li0 = 1.f / l0, li1 = 1.f / l1;
    int n_lo = qbase + r0 + g;
    int n_hi = n_lo + 8;
    float* out_lo = out + ((size_t)b * SEQ + n_lo) * EMBED + h * HEAD_DIM;
    float* out_hi = out + ((size_t)b * SEQ + n_hi) * EMBED + h * HEAD_DIM;
#pragma unroll
    for (int nt = 0; nt < 8; nt++) {
        int d = nt * 8 + 2 * t;
        float2 v0; v0.x = O[nt][0] * li0; v0.y = O[nt][1] * li0;
        float2 v1; v1.x = O[nt][2] * li1; v1.y = O[nt][3] * li1;
        *(float2*)&out_lo[d] = v0;
        *(float2*)&out_hi[d] = v1;
    }
}

extern "C" void kernel_launch(void* const* d_in, const int* in_sizes, int n_in,
                              void* d_out, int out_size)
{
    const float* query = (const float*)d_in[0];
    const float* key   = (const float*)d_in[1];
    const float* value = (const float*)d_in[2];
    const float* Wq = (const float*)d_in[3];
    const float* bq = (const float*)d_in[4];
    const float* Wk = (const float*)d_in[5];
    const float* bk = (const float*)d_in[6];
    const float* Wv = (const float*)d_in[7];
    const float* bv = (const float*)d_in[8];
    float* out = (float*)d_out;

    (void)in_sizes; (void)n_in; (void)out_size;

    // Resolve device-global scratch addresses
    float *xr, *wr;
    cudaGetSymbolAddress((void**)&xr, g_xr);
    cudaGetSymbolAddress((void**)&wr, g_wr);

    // Stage 0: tf32 prepass (X: 1M float4 each; W: 256K float4 each)
    const int NX4 = MTOT * EMBED / 4, NW4 = EMBED * EMBED / 4;
    round_kernel<<<2048, 256>>>((const float4*)query, (float4*)(xr + 0 * (size_t)MTOT * EMBED), NX4);
    round_kernel<<<2048, 256>>>((const float4*)key,   (float4*)(xr + 1 * (size_t)MTOT * EMBED), NX4);
    round_kernel<<<2048, 256>>>((const float4*)value, (float4*)(xr + 2 * (size_t)MTOT * EMBED), NX4);
    round_kernel<<<1024, 256>>>((const float4*)Wq,    (float4*)(wr + 0 * (size_t)EMBED * EMBED), NW4);
    round_kernel<<<1024, 256>>>((const float4*)Wk,    (float4*)(wr + 1 * (size_t)EMBED * EMBED), NW4);
    round_kernel<<<1024, 256>>>((const float4*)Wv,    (float4*)(wr + 2 * (size_t)EMBED * EMBED), NW4);

    cudaFuncSetAttribute(qkv_gemm_kernel, cudaFuncAttributeMaxDynamicSharedMemorySize,
                         (int)QKV_SMEM);
    cudaFuncSetAttribute(attn_kernel, cudaFuncAttributeMaxDynamicSharedMemorySize,
                         (int)ATTN_SMEM);

    // Stage A: QKV projections (z = 0/1/2 -> q/k/vt)
    dim3 ggrid(EMBED / 128, MTOT / 128, 3);
    qkv_gemm_kernel<<<ggrid, 256, QKV_SMEM>>>(bq, bk, bv);

    // Stage B: flash attention
    dim3 agrid(SEQ / 128, HEADS, BATCH);
    attn_kernel<<<agrid, 256, ATTN_SMEM>>>(out);
}

// round 15
// speedup vs baseline: 3.0245x; 1.5654x over previous
#include <cuda_runtime.h>
#include <cuda_fp16.h>

#define EMBED 1024
#define HEADS 16
#define HEAD_DIM 64
#define BATCH 2
#define SEQ 2048
#define MTOT (BATCH * SEQ)   // 4096

// Projected Q/K in [B,H,N,Dh]; V transposed as VT in [B,H,Dh,N]. All fp16.
// Q pre-scaled by Dh^-0.5.
__device__ __half g_q [BATCH * HEADS * SEQ * HEAD_DIM];
__device__ __half g_k [BATCH * HEADS * SEQ * HEAD_DIM];
__device__ __half g_vt[BATCH * HEADS * HEAD_DIM * SEQ];
// fp16 copies of inputs (prepass) so GEMM smem holds raw fp16 for ldsm.
__device__ __half g_xr[3 * MTOT * EMBED];
__device__ __half g_wr[3 * EMBED * EMBED];

__device__ __forceinline__ unsigned packh2(float lo, float hi) {
    __half2 h = __floats2half2_rn(lo, hi);
    return *(unsigned*)&h;
}

__device__ __forceinline__ void mma_f16(float c[4],
                                        unsigned a0, unsigned a1, unsigned a2, unsigned a3,
                                        unsigned b0, unsigned b1) {
    asm volatile(
        "mma.sync.aligned.m16n8k16.row.col.f32.f16.f16.f32 "
        "{%0,%1,%2,%3},{%4,%5,%6,%7},{%8,%9},{%0,%1,%2,%3};"
        : "+f"(c[0]), "+f"(c[1]), "+f"(c[2]), "+f"(c[3])
        : "r"(a0), "r"(a1), "r"(a2), "r"(a3), "r"(b0), "r"(b1));
}

__device__ __forceinline__ void ldsm4(unsigned& r0, unsigned& r1, unsigned& r2, unsigned& r3,
                                      unsigned addr) {
    asm volatile("ldmatrix.sync.aligned.m8n8.x4.shared.b16 {%0,%1,%2,%3}, [%4];"
                 : "=r"(r0), "=r"(r1), "=r"(r2), "=r"(r3) : "r"(addr));
}

#define CP_ASYNC16(dst_u32, src_ptr) \
    asm volatile("cp.async.ca.shared.global [%0], [%1], 16;" :: "r"(dst_u32), "l"(src_ptr))
#define CP_COMMIT() asm volatile("cp.async.commit_group;")
#define CP_WAIT0()  asm volatile("cp.async.wait_group 0;")

#define STG_CS32(ptr, val) \
    asm volatile("st.global.cs.u32 [%0], %1;" :: "l"(ptr), "r"(val))
#define STG_CS16(ptr, val) \
    asm volatile("st.global.cs.u16 [%0], %1;" :: "l"(ptr), "h"(val))

// ============================================================================
// Stage 0: prepass — convert X and W to fp16 once (RN, same 10-bit mantissa
// precision as the tf32 path; all accumulation stays fp32).
// ============================================================================
__global__ void cvt_kernel(const float4* __restrict__ src, uint2* __restrict__ dst, int n4)
{
    int i = blockIdx.x * blockDim.x + threadIdx.x;
    int stride = gridDim.x * blockDim.x;
    for (; i < n4; i += stride) {
        float4 v = src[i];
        uint2 o;
        o.x = packh2(v.x, v.y);
        o.y = packh2(v.z, v.w);
        dst[i] = o;
    }
}

// ============================================================================
// Stage A: QKV projection via fp16 m16n8k16 MMA, pure-LDSM.
// 128x128 tile, K-tile 32, cp.async double buffered, 2 CTAs/SM.
// z=0 -> g_q (scaled 1/8), z=1 -> g_k, z=2 -> g_vt (transposed scatter).
// ============================================================================
#define ASTR 40                     // halves; 80B = 5x16B rows: odd -> ldsm conflict-free
#define QKV_TILE (128 * ASTR)       // halves per tile buffer
#define QKV_SMEM (4 * QKV_TILE * sizeof(__half))   // 40960 B

__global__ void __launch_bounds__(256, 2) qkv_gemm_kernel(
    const float* __restrict__ bq, const float* __restrict__ bk, const float* __restrict__ bv)
{
    extern __shared__ __half smem[];
    __half* sAb[2] = { smem,                smem + QKV_TILE };
    __half* sBb[2] = { smem + 2 * QKV_TILE, smem + 3 * QKV_TILE };

    const int z = blockIdx.z;
    const __half* X    = g_xr + (size_t)z * MTOT * EMBED;
    const __half* W    = g_wr + (size_t)z * EMBED * EMBED;
    const float* bias  = (z == 0) ? bq : (z == 1) ? bk : bv;
    const float scale  = (z == 0) ? 0.125f : 1.0f;

    const int rowBase = blockIdx.y * 128;
    const int colBase = blockIdx.x * 128;
    const int tid  = threadIdx.x;
    const int warp = tid >> 5, lane = tid & 31;
    const int wm = warp >> 1, wn = warp & 1;
    const int g = lane >> 2, t = lane & 3;
    const int lr = lane & 7, mi = lane >> 3;
    // ldsm.x4 lane addressing: tiles (rows lo/hi) x (k-halves lo/hi)
    const int m_row = lr + ((mi & 1) << 3);
    const int m_col = (mi >> 1) << 3;           // in halves

    const unsigned aB[2] = { (unsigned)__cvta_generic_to_shared(sAb[0]),
                             (unsigned)__cvta_generic_to_shared(sAb[1]) };
    const unsigned bB[2] = { (unsigned)__cvta_generic_to_shared(sBb[0]),
                             (unsigned)__cvta_generic_to_shared(sBb[1]) };

    float C[2][8][4];
#pragma unroll
    for (int i = 0; i < 2; i++)
#pragma unroll
        for (int j = 0; j < 8; j++)
#pragma unroll
            for (int k = 0; k < 4; k++) C[i][j][k] = 0.f;

    auto load_tile = [&](int k0, int bi) {
        unsigned sa = aB[bi], sb = bB[bi];
#pragma unroll
        for (int i = 0; i < 2; i++) {
            int idx = tid + i * 256;         // 512 chunks each (128 rows x 4)
            int r = idx >> 2;
            int c8 = (idx & 3) * 8;          // halves
            CP_ASYNC16(sa + (r * ASTR + c8) * 2, X + (size_t)(rowBase + r) * EMBED + k0 + c8);
            CP_ASYNC16(sb + (r * ASTR + c8) * 2, W + (size_t)(colBase + r) * EMBED + k0 + c8);
        }
    };

    load_tile(0, 0); CP_COMMIT();

    for (int kt = 0; kt < EMBED / 32; kt++) {
        CP_WAIT0();
        __syncthreads();
        if (kt + 1 < EMBED / 32) { load_tile((kt + 1) * 32, (kt + 1) & 1); CP_COMMIT(); }

        const unsigned aBase = aB[kt & 1];
        const unsigned bBase = bB[kt & 1];

#pragma unroll
        for (int kk = 0; kk < 32; kk += 16) {
            unsigned a[2][4];
#pragma unroll
            for (int mt = 0; mt < 2; mt++)
                ldsm4(a[mt][0], a[mt][1], a[mt][2], a[mt][3],
                      aBase + (((wm * 32 + mt * 16) + m_row) * ASTR + kk + m_col) * 2);
#pragma unroll
            for (int np = 0; np < 4; np++) {
                unsigned b0e, b0o, b1e, b1o;   // n-group even/odd, k lo/hi
                ldsm4(b0e, b0o, b1e, b1o,
                      bBase + (((wn * 64 + np * 16) + m_row) * ASTR + kk + m_col) * 2);
                mma_f16(C[0][2 * np],     a[0][0], a[0][1], a[0][2], a[0][3], b0e, b1e);
                mma_f16(C[1][2 * np],     a[1][0], a[1][1], a[1][2], a[1][3], b0e, b1e);
                mma_f16(C[0][2 * np + 1], a[0][0], a[0][1], a[0][2], a[0][3], b0o, b1o);
                mma_f16(C[1][2 * np + 1], a[1][0], a[1][1], a[1][2], a[1][3], b0o, b1o);
            }
        }
    }

    // Epilogue: bias, scale (fp32), convert fp16, scatter (Q/K normal, V transposed)
#pragma unroll
    for (int mt = 0; mt < 2; mt++) {
#pragma unroll
        for (int nt = 0; nt < 8; nt++) {
            int col = colBase + wn * 64 + nt * 8 + 2 * t;
            float b0v = bias[col], b1v = bias[col + 1];
            int h = col >> 6;
            int d = col & 63;
#pragma unroll
            for (int half = 0; half < 2; half++) {
                int row = rowBase + wm * 32 + mt * 16 + g + half * 8;
                int b = row >> 11;
                int n = row & (SEQ - 1);
                int bh = b * HEADS + h;
                float v0 = (C[mt][nt][half * 2 + 0] + b0v) * scale;
                float v1 = (C[mt][nt][half * 2 + 1] + b1v) * scale;
                if (z < 2) {
                    __half* dst = (z == 0) ? g_q : g_k;
                    STG_CS32(&dst[(((size_t)bh) * SEQ + n) * HEAD_DIM + d], packh2(v0, v1));
                } else {
                    __half h0 = __float2half_rn(v0), h1 = __float2half_rn(v1);
                    STG_CS16(&g_vt[(((size_t)bh) * HEAD_DIM + d)     * SEQ + n], *(unsigned short*)&h0);
                    STG_CS16(&g_vt[(((size_t)bh) * HEAD_DIM + d + 1) * SEQ + n], *(unsigned short*)&h1);
                }
            }
        }
    }
}

// ============================================================================
// Stage B: flash attention, fp16 m16n8k16, register softmax.
// CTA = (b, h, 128 q-rows). 8 warps x 16 rows. 32 key tiles of 64.
// cp.async double buffered, 2 CTAs/SM. Sc fp32 packs straight into PV A-frags.
// ============================================================================
#define KSTR 72                 // halves; 144B = 9x16B rows: odd -> conflict-free
#define VTSTR 72
#define BK 64
#define SQ_F (128 * KSTR)       // 9216 halves
#define KT_F (BK * KSTR)        // 4608 halves
#define VT_F (HEAD_DIM * VTSTR) // 4608 halves
#define SK0_OFF SQ_F
#define SK1_OFF (SQ_F + KT_F)
#define SV0_OFF (SQ_F + 2 * KT_F)
#define SV1_OFF (SQ_F + 2 * KT_F + VT_F)
#define ATTN_SMEM ((SQ_F + 2 * KT_F + 2 * VT_F) * sizeof(__half))   // 55296 B

__global__ void __launch_bounds__(256, 2) attn_kernel(float* __restrict__ out)
{
    extern __shared__ __half smem[];

    const int qtile = blockIdx.x;
    const int h = blockIdx.y;
    const int b = blockIdx.z;
    const int bh = b * HEADS + h;
    const __half* Qg  = g_q  + (size_t)bh * SEQ * HEAD_DIM;
    const __half* Kg  = g_k  + (size_t)bh * SEQ * HEAD_DIM;
    const __half* VTg = g_vt + (size_t)bh * HEAD_DIM * SEQ;

    const int tid = threadIdx.x, warp = tid >> 5, lane = tid & 31;
    const int g = lane >> 2, t = lane & 3;
    const int lr = lane & 7, mi = lane >> 3;
    const int m_row = lr + ((mi & 1) << 3);
    const int m_col = (mi >> 1) << 3;          // halves
    const int r0 = warp * 16;
    const int qbase = qtile * 128;

    const unsigned sqB = (unsigned)__cvta_generic_to_shared(smem);
    const unsigned skB[2] = { (unsigned)__cvta_generic_to_shared(smem + SK0_OFF),
                              (unsigned)__cvta_generic_to_shared(smem + SK1_OFF) };
    const unsigned svB[2] = { (unsigned)__cvta_generic_to_shared(smem + SV0_OFF),
                              (unsigned)__cvta_generic_to_shared(smem + SV1_OFF) };

    // Q tile (128 x 64 halves) via cp.async
#pragma unroll
    for (int i = 0; i < 4; i++) {
        int idx = tid + i * 256;               // 1024 chunks (8 per row)
        int r = idx >> 3;
        int c8 = (idx & 7) * 8;
        CP_ASYNC16(sqB + (r * KSTR + c8) * 2, Qg + (size_t)(qbase + r) * HEAD_DIM + c8);
    }

    float O[8][4];
#pragma unroll
    for (int j = 0; j < 8; j++)
#pragma unroll
        for (int k = 0; k < 4; k++) O[j][k] = 0.f;
    float m0 = -1e30f, m1 = -1e30f, l0 = 0.f, l1 = 0.f;

    auto load_tile = [&](int kbase, int bi) {
        unsigned sk = skB[bi], sv = svB[bi];
#pragma unroll
        for (int i = 0; i < 2; i++) {
            int idx = tid + i * 256;           // 512 chunks each (64 rows x 8)
            int r = idx >> 3;
            int c8 = (idx & 7) * 8;
            CP_ASYNC16(sk + (r * KSTR  + c8) * 2, Kg  + (size_t)(kbase + r) * HEAD_DIM + c8);
            CP_ASYNC16(sv + (r * VTSTR + c8) * 2, VTg + (size_t)r * SEQ + kbase + c8);
        }
    };

    load_tile(0, 0); CP_COMMIT();

    for (int kt = 0; kt < SEQ / BK; kt++) {
        CP_WAIT0();
        __syncthreads();
        if (kt + 1 < SEQ / BK) { load_tile((kt + 1) * BK, (kt + 1) & 1); CP_COMMIT(); }

        const unsigned kBase = skB[kt & 1];
        const unsigned vBase = svB[kt & 1];

        // ---- S = Q K^T : 4 k-steps of 16 ----
        float Sc[8][4];
#pragma unroll
        for (int j = 0; j < 8; j++)
#pragma unroll
            for (int k = 0; k < 4; k++) Sc[j][k] = 0.f;

#pragma unroll
        for (int kk = 0; kk < HEAD_DIM; kk += 16) {
            unsigned a0, a1, a2, a3;
            ldsm4(a0, a1, a2, a3, sqB + ((r0 + m_row) * KSTR + kk + m_col) * 2);
#pragma unroll
            for (int np = 0; np < 4; np++) {
                unsigned b0e, b0o, b1e, b1o;
                ldsm4(b0e, b0o, b1e, b1o,
                      kBase + ((np * 16 + m_row) * KSTR + kk + m_col) * 2);
                mma_f16(Sc[2 * np],     a0, a1, a2, a3, b0e, b1e);
                mma_f16(Sc[2 * np + 1], a0, a1, a2, a3, b0o, b1o);
            }
        }

        // ---- Online softmax, fully in registers ----
        float mx0 = -1e30f, mx1 = -1e30f;
#pragma unroll
        for (int nt = 0; nt < 8; nt++) {
            mx0 = fmaxf(mx0, fmaxf(Sc[nt][0], Sc[nt][1]));
            mx1 = fmaxf(mx1, fmaxf(Sc[nt][2], Sc[nt][3]));
        }
        mx0 = fmaxf(mx0, __shfl_xor_sync(0xFFFFFFFFu, mx0, 1));
        mx0 = fmaxf(mx0, __shfl_xor_sync(0xFFFFFFFFu, mx0, 2));
        mx1 = fmaxf(mx1, __shfl_xor_sync(0xFFFFFFFFu, mx1, 1));
        mx1 = fmaxf(mx1, __shfl_xor_sync(0xFFFFFFFFu, mx1, 2));

        float mn0 = fmaxf(m0, mx0), mn1 = fmaxf(m1, mx1);
        float f0 = __expf(m0 - mn0), f1 = __expf(m1 - mn1);

        float s0 = 0.f, s1 = 0.f;
#pragma unroll
        for (int nt = 0; nt < 8; nt++) {
            Sc[nt][0] = __expf(Sc[nt][0] - mn0); s0 += Sc[nt][0];
            Sc[nt][1] = __expf(Sc[nt][1] - mn0); s0 += Sc[nt][1];
            Sc[nt][2] = __expf(Sc[nt][2] - mn1); s1 += Sc[nt][2];
            Sc[nt][3] = __expf(Sc[nt][3] - mn1); s1 += Sc[nt][3];
        }
        s0 += __shfl_xor_sync(0xFFFFFFFFu, s0, 1);
        s0 += __shfl_xor_sync(0xFFFFFFFFu, s0, 2);
        s1 += __shfl_xor_sync(0xFFFFFFFFu, s1, 1);
        s1 += __shfl_xor_sync(0xFFFFFFFFu, s1, 2);

        l0 = l0 * f0 + s0;  l1 = l1 * f1 + s1;
        m0 = mn0;           m1 = mn1;

#pragma unroll
        for (int nt = 0; nt < 8; nt++) {
            O[nt][0] *= f0; O[nt][1] *= f0;
            O[nt][2] *= f1; O[nt][3] *= f1;
        }

        // ---- O += P V : pack Sc pairs into fp16 A-frags; VT via ldsm ----
#pragma unroll
        for (int j = 0; j < 4; j++) {           // k-chunks of 16 keys
            unsigned a0 = packh2(Sc[2 * j][0],     Sc[2 * j][1]);
            unsigned a1 = packh2(Sc[2 * j][2],     Sc[2 * j][3]);
            unsigned a2 = packh2(Sc[2 * j + 1][0], Sc[2 * j + 1][1]);
            unsigned a3 = packh2(Sc[2 * j + 1][2], Sc[2 * j + 1][3]);
#pragma unroll
            for (int np = 0; np < 4; np++) {    // dh-groups of 16
                unsigned b0e, b0o, b1e, b1o;
                ldsm4(b0e, b0o, b1e, b1o,
                      vBase + ((np * 16 + m_row) * VTSTR + j * 16 + m_col) * 2);
                mma_f16(O[2 * np],     a0, a1, a2, a3, b0e, b1e);
                mma_f16(O[2 * np + 1], a0, a1, a2, a3, b0o, b1o);
            }
        }
    }

    // ---- Epilogue: O /= l, write [B, N, E] (float2 stores, fp32) ----
    float li0 = 1.f / l0, li1 = 1.f / l1;
    int n_lo = qbase + r0 + g;
    int n_hi = n_lo + 8;
    float* out_lo = out + ((size_t)b * SEQ + n_lo) * EMBED + h * HEAD_DIM;
    float* out_hi = out + ((size_t)b * SEQ + n_hi) * EMBED + h * HEAD_DIM;
#pragma unroll
    for (int nt = 0; nt < 8; nt++) {
        int d = nt * 8 + 2 * t;
        float2 v0; v0.x = O[nt][0] * li0; v0.y = O[nt][1] * li0;
        float2 v1; v1.x = O[nt][2] * li1; v1.y = O[nt][3] * li1;
        *(float2*)&out_lo[d] = v0;
        *(float2*)&out_hi[d] = v1;
    }
}

extern "C" void kernel_launch(void* const* d_in, const int* in_sizes, int n_in,
                              void* d_out, int out_size)
{
    const float* query = (const float*)d_in[0];
    const float* key   = (const float*)d_in[1];
    const float* value = (const float*)d_in[2];
    const float* Wq = (const float*)d_in[3];
    const float* bq = (const float*)d_in[4];
    const float* Wk = (const float*)d_in[5];
    const float* bk = (const float*)d_in[6];
    const float* Wv = (const float*)d_in[7];
    const float* bv = (const float*)d_in[8];
    float* out = (float*)d_out;

    (void)in_sizes; (void)n_in; (void)out_size;

    __half *xr, *wr;
    cudaGetSymbolAddress((void**)&xr, g_xr);
    cudaGetSymbolAddress((void**)&wr, g_wr);

    // Stage 0: fp16 prepass
    const int NX4 = MTOT * EMBED / 4, NW4 = EMBED * EMBED / 4;
    cvt_kernel<<<2048, 256>>>((const float4*)query, (uint2*)(xr + 0 * (size_t)MTOT * EMBED), NX4);
    cvt_kernel<<<2048, 256>>>((const float4*)key,   (uint2*)(xr + 1 * (size_t)MTOT * EMBED), NX4);
    cvt_kernel<<<2048, 256>>>((const float4*)value, (uint2*)(xr + 2 * (size_t)MTOT * EMBED), NX4);
    cvt_kernel<<<1024, 256>>>((const float4*)Wq,    (uint2*)(wr + 0 * (size_t)EMBED * EMBED), NW4);
    cvt_kernel<<<1024, 256>>>((const float4*)Wk,    (uint2*)(wr + 1 * (size_t)EMBED * EMBED), NW4);
    cvt_kernel<<<1024, 256>>>((const float4*)Wv,    (uint2*)(wr + 2 * (size_t)EMBED * EMBED), NW4);

    cudaFuncSetAttribute(qkv_gemm_kernel, cudaFuncAttributeMaxDynamicSharedMemorySize,
                         (int)QKV_SMEM);
    cudaFuncSetAttribute(attn_kernel, cudaFuncAttributeMaxDynamicSharedMemorySize,
                         (int)ATTN_SMEM);

    // Stage A: QKV projections (z = 0/1/2 -> q/k/vt)
    dim3 ggrid(EMBED / 128, MTOT / 128, 3);
    qkv_gemm_kernel<<<ggrid, 256, QKV_SMEM>>>(bq, bk, bv);

    // Stage B: flash attention
    dim3 agrid(SEQ / 128, HEADS, BATCH);
    attn_kernel<<<agrid, 256, ATTN_SMEM>>>(out);
}

// round 17
// speedup vs baseline: 3.1844x; 1.0529x over previous
#include <cuda_runtime.h>
#include <cuda_fp16.h>

#define EMBED 1024
#define HEADS 16
#define HEAD_DIM 64
#define BATCH 2
#define SEQ 2048
#define MTOT (BATCH * SEQ)   // 4096

// Projected Q/K in [B,H,N,Dh]; V transposed as VT in [B,H,Dh,N]. All fp16.
// Q pre-scaled by Dh^-0.5 * log2(e) (softmax uses exp2).
__device__ __half g_q [BATCH * HEADS * SEQ * HEAD_DIM];
__device__ __half g_k [BATCH * HEADS * SEQ * HEAD_DIM];
__device__ __half g_vt[BATCH * HEADS * HEAD_DIM * SEQ];
// fp16 copies of inputs (prepass) so GEMM smem holds raw fp16 for ldsm.
__device__ __half g_xr[3 * MTOT * EMBED];
__device__ __half g_wr[3 * EMBED * EMBED];

#define LOG2E 1.4426950408889634f

__device__ __forceinline__ unsigned packh2(float lo, float hi) {
    __half2 h = __floats2half2_rn(lo, hi);
    return *(unsigned*)&h;
}

__device__ __forceinline__ void mma_f16(float c[4],
                                        unsigned a0, unsigned a1, unsigned a2, unsigned a3,
                                        unsigned b0, unsigned b1) {
    asm volatile(
        "mma.sync.aligned.m16n8k16.row.col.f32.f16.f16.f32 "
        "{%0,%1,%2,%3},{%4,%5,%6,%7},{%8,%9},{%0,%1,%2,%3};"
        : "+f"(c[0]), "+f"(c[1]), "+f"(c[2]), "+f"(c[3])
        : "r"(a0), "r"(a1), "r"(a2), "r"(a3), "r"(b0), "r"(b1));
}

__device__ __forceinline__ void ldsm4(unsigned& r0, unsigned& r1, unsigned& r2, unsigned& r3,
                                      unsigned addr) {
    asm volatile("ldmatrix.sync.aligned.m8n8.x4.shared.b16 {%0,%1,%2,%3}, [%4];"
                 : "=r"(r0), "=r"(r1), "=r"(r2), "=r"(r3) : "r"(addr));
}

#define CP_ASYNC16(dst_u32, src_ptr) \
    asm volatile("cp.async.ca.shared.global [%0], [%1], 16;" :: "r"(dst_u32), "l"(src_ptr))
#define CP_COMMIT() asm volatile("cp.async.commit_group;")
#define CP_WAIT1()  asm volatile("cp.async.wait_group 1;")

#define STG_CS32(ptr, val) \
    asm volatile("st.global.cs.u32 [%0], %1;" :: "l"(ptr), "r"(val))
#define STG_CS16(ptr, val) \
    asm volatile("st.global.cs.u16 [%0], %1;" :: "l"(ptr), "h"(val))

// ============================================================================
// Stage 0: prepass — convert 3 tensors to fp16 in one launch (blockIdx.y).
// ============================================================================
__global__ void cvt3_kernel(const float4* __restrict__ s0, const float4* __restrict__ s1,
                            const float4* __restrict__ s2,
                            uint2* __restrict__ d0, uint2* __restrict__ d1,
                            uint2* __restrict__ d2, int n4)
{
    const float4* src = (blockIdx.y == 0) ? s0 : (blockIdx.y == 1) ? s1 : s2;
    uint2*        dst = (blockIdx.y == 0) ? d0 : (blockIdx.y == 1) ? d1 : d2;
    int i = blockIdx.x * blockDim.x + threadIdx.x;
    int stride = gridDim.x * blockDim.x;
    for (; i < n4; i += stride) {
        float4 v = src[i];
        uint2 o;
        o.x = packh2(v.x, v.y);
        o.y = packh2(v.z, v.w);
        dst[i] = o;
    }
}

// ============================================================================
// Stage A: QKV projection via fp16 m16n8k16 MMA, pure-LDSM.
// 128x128 tile, K-tile 32, cp.async TRIPLE buffered, 2 CTAs/SM.
// z=0 -> g_q (scaled log2e/8), z=1 -> g_k, z=2 -> g_vt (transposed scatter).
// ============================================================================
#define ASTR 40                     // halves; 80B = 5x16B rows: odd -> ldsm conflict-free
#define QKV_TILE (128 * ASTR)       // halves per tile buffer
#define QKV_SMEM (6 * QKV_TILE * sizeof(__half))   // 61440 B (3 A + 3 B)

__global__ void __launch_bounds__(256, 2) qkv_gemm_kernel(
    const float* __restrict__ bq, const float* __restrict__ bk, const float* __restrict__ bv)
{
    extern __shared__ __half smem[];

    const int z = blockIdx.z;
    const __half* X    = g_xr + (size_t)z * MTOT * EMBED;
    const __half* W    = g_wr + (size_t)z * EMBED * EMBED;
    const float* bias  = (z == 0) ? bq : (z == 1) ? bk : bv;
    const float scale  = (z == 0) ? 0.125f * LOG2E : 1.0f;

    const int rowBase = blockIdx.y * 128;
    const int colBase = blockIdx.x * 128;
    const int tid  = threadIdx.x;
    const int warp = tid >> 5, lane = tid & 31;
    const int wm = warp >> 1, wn = warp & 1;
    const int g = lane >> 2, t = lane & 3;
    const int lr = lane & 7, mi = lane >> 3;
    const int m_row = lr + ((mi & 1) << 3);
    const int m_col = (mi >> 1) << 3;           // in halves

    unsigned aB[3], bB[3];
#pragma unroll
    for (int i = 0; i < 3; i++) {
        aB[i] = (unsigned)__cvta_generic_to_shared(smem + i * QKV_TILE);
        bB[i] = (unsigned)__cvta_generic_to_shared(smem + (3 + i) * QKV_TILE);
    }

    float C[2][8][4];
#pragma unroll
    for (int i = 0; i < 2; i++)
#pragma unroll
        for (int j = 0; j < 8; j++)
#pragma unroll
            for (int k = 0; k < 4; k++) C[i][j][k] = 0.f;

    auto load_tile = [&](int k0, int bi) {
        unsigned sa = aB[bi], sb = bB[bi];
#pragma unroll
        for (int i = 0; i < 2; i++) {
            int idx = tid + i * 256;         // 512 chunks each (128 rows x 4)
            int r = idx >> 2;
            int c8 = (idx & 3) * 8;          // halves
            CP_ASYNC16(sa + (r * ASTR + c8) * 2, X + (size_t)(rowBase + r) * EMBED + k0 + c8);
            CP_ASYNC16(sb + (r * ASTR + c8) * 2, W + (size_t)(colBase + r) * EMBED + k0 + c8);
        }
    };

    load_tile(0, 0);  CP_COMMIT();
    load_tile(32, 1); CP_COMMIT();

    for (int kt = 0; kt < EMBED / 32; kt++) {
        CP_WAIT1();                 // tile kt complete; kt+1 may stay in flight
        __syncthreads();
        if (kt + 2 < EMBED / 32) { load_tile((kt + 2) * 32, (kt + 2) % 3); CP_COMMIT(); }

        const int bi = kt % 3;
        const unsigned aBase = aB[bi];
        const unsigned bBase = bB[bi];

#pragma unroll
        for (int kk = 0; kk < 32; kk += 16) {
            unsigned a[2][4];
#pragma unroll
            for (int mt = 0; mt < 2; mt++)
                ldsm4(a[mt][0], a[mt][1], a[mt][2], a[mt][3],
                      aBase + (((wm * 32 + mt * 16) + m_row) * ASTR + kk + m_col) * 2);
#pragma unroll
            for (int np = 0; np < 4; np++) {
                unsigned b0e, b0o, b1e, b1o;   // n-group even/odd, k lo/hi
                ldsm4(b0e, b0o, b1e, b1o,
                      bBase + (((wn * 64 + np * 16) + m_row) * ASTR + kk + m_col) * 2);
                mma_f16(C[0][2 * np],     a[0][0], a[0][1], a[0][2], a[0][3], b0e, b1e);
                mma_f16(C[1][2 * np],     a[1][0], a[1][1], a[1][2], a[1][3], b0e, b1e);
                mma_f16(C[0][2 * np + 1], a[0][0], a[0][1], a[0][2], a[0][3], b0o, b1o);
                mma_f16(C[1][2 * np + 1], a[1][0], a[1][1], a[1][2], a[1][3], b0o, b1o);
            }
        }
    }

    // Epilogue: bias, scale (fp32), convert fp16, scatter (Q/K normal, V transposed)
#pragma unroll
    for (int mt = 0; mt < 2; mt++) {
#pragma unroll
        for (int nt = 0; nt < 8; nt++) {
            int col = colBase + wn * 64 + nt * 8 + 2 * t;
            float b0v = bias[col], b1v = bias[col + 1];
            int h = col >> 6;
            int d = col & 63;
#pragma unroll
            for (int half = 0; half < 2; half++) {
                int row = rowBase + wm * 32 + mt * 16 + g + half * 8;
                int b = row >> 11;
                int n = row & (SEQ - 1);
                int bh = b * HEADS + h;
                float v0 = (C[mt][nt][half * 2 + 0] + b0v) * scale;
                float v1 = (C[mt][nt][half * 2 + 1] + b1v) * scale;
                if (z < 2) {
                    __half* dst = (z == 0) ? g_q : g_k;
                    STG_CS32(&dst[(((size_t)bh) * SEQ + n) * HEAD_DIM + d], packh2(v0, v1));
                } else {
                    __half h0 = __float2half_rn(v0), h1 = __float2half_rn(v1);
                    STG_CS16(&g_vt[(((size_t)bh) * HEAD_DIM + d)     * SEQ + n], *(unsigned short*)&h0);
                    STG_CS16(&g_vt[(((size_t)bh) * HEAD_DIM + d + 1) * SEQ + n], *(unsigned short*)&h1);
                }
            }
        }
    }
}

// ============================================================================
// Stage B: flash attention, fp16 m16n8k16, register softmax (exp2 domain).
// CTA = (b, h, 128 q-rows). 8 warps x 16 rows. 32 key tiles of 64.
// cp.async TRIPLE buffered, 2 CTAs/SM. Sc fp32 packs straight into PV A-frags.
// ============================================================================
#define KSTR 72                 // halves; 144B = 9x16B rows: odd -> conflict-free
#define VTSTR 72
#define BK 64
#define SQ_F (128 * KSTR)       // 9216 halves
#define KT_F (BK * KSTR)        // 4608 halves
#define VT_F (HEAD_DIM * VTSTR) // 4608 halves
#define ATTN_SMEM ((SQ_F + 3 * KT_F + 3 * VT_F) * sizeof(__half))   // 73728 B

__global__ void __launch_bounds__(256, 2) attn_kernel(float* __restrict__ out)
{
    extern __shared__ __half smem[];

    const int qtile = blockIdx.x;
    const int h = blockIdx.y;
    const int b = blockIdx.z;
    const int bh = b * HEADS + h;
    const __half* Qg  = g_q  + (size_t)bh * SEQ * HEAD_DIM;
    const __half* Kg  = g_k  + (size_t)bh * SEQ * HEAD_DIM;
    const __half* VTg = g_vt + (size_t)bh * HEAD_DIM * SEQ;

    const int tid = threadIdx.x, warp = tid >> 5, lane = tid & 31;
    const int g = lane >> 2, t = lane & 3;
    const int lr = lane & 7, mi = lane >> 3;
    const int m_row = lr + ((mi & 1) << 3);
    const int m_col = (mi >> 1) << 3;          // halves
    const int r0 = warp * 16;
    const int qbase = qtile * 128;

    const unsigned sqB = (unsigned)__cvta_generic_to_shared(smem);
    unsigned skB[3], svB[3];
#pragma unroll
    for (int i = 0; i < 3; i++) {
        skB[i] = (unsigned)__cvta_generic_to_shared(smem + SQ_F + i * KT_F);
        svB[i] = (unsigned)__cvta_generic_to_shared(smem + SQ_F + 3 * KT_F + i * VT_F);
    }

    // Q tile (128 x 64 halves) via cp.async — rides in commit group 0
#pragma unroll
    for (int i = 0; i < 4; i++) {
        int idx = tid + i * 256;               // 1024 chunks (8 per row)
        int r = idx >> 3;
        int c8 = (idx & 7) * 8;
        CP_ASYNC16(sqB + (r * KSTR + c8) * 2, Qg + (size_t)(qbase + r) * HEAD_DIM + c8);
    }

    float O[8][4];
#pragma unroll
    for (int j = 0; j < 8; j++)
#pragma unroll
        for (int k = 0; k < 4; k++) O[j][k] = 0.f;
    float m0 = -1e30f, m1 = -1e30f, l0 = 0.f, l1 = 0.f;

    auto load_tile = [&](int kbase, int bi) {
        unsigned sk = skB[bi], sv = svB[bi];
#pragma unroll
        for (int i = 0; i < 2; i++) {
            int idx = tid + i * 256;           // 512 chunks each (64 rows x 8)
            int r = idx >> 3;
            int c8 = (idx & 7) * 8;
            CP_ASYNC16(sk + (r * KSTR  + c8) * 2, Kg  + (size_t)(kbase + r) * HEAD_DIM + c8);
            CP_ASYNC16(sv + (r * VTSTR + c8) * 2, VTg + (size_t)r * SEQ + kbase + c8);
        }
    };

    load_tile(0, 0);  CP_COMMIT();             // group 0 = Q + tile0
    load_tile(BK, 1); CP_COMMIT();             // group 1 = tile1

    for (int kt = 0; kt < SEQ / BK; kt++) {
        CP_WAIT1();                 // tile kt (and Q) complete
        __syncthreads();
        if (kt + 2 < SEQ / BK) { load_tile((kt + 2) * BK, (kt + 2) % 3); CP_COMMIT(); }

        const int bi = kt % 3;
        const unsigned kBase = skB[bi];
        const unsigned vBase = svB[bi];

        // ---- S = Q K^T : 4 k-steps of 16 ----
        float Sc[8][4];
#pragma unroll
        for (int j = 0; j < 8; j++)
#pragma unroll
            for (int k = 0; k < 4; k++) Sc[j][k] = 0.f;

#pragma unroll
        for (int kk = 0; kk < HEAD_DIM; kk += 16) {
            unsigned a0, a1, a2, a3;
            ldsm4(a0, a1, a2, a3, sqB + ((r0 + m_row) * KSTR + kk + m_col) * 2);
#pragma unroll
            for (int np = 0; np < 4; np++) {
                unsigned b0e, b0o, b1e, b1o;
                ldsm4(b0e, b0o, b1e, b1o,
                      kBase + ((np * 16 + m_row) * KSTR + kk + m_col) * 2);
                mma_f16(Sc[2 * np],     a0, a1, a2, a3, b0e, b1e);
                mma_f16(Sc[2 * np + 1], a0, a1, a2, a3, b0o, b1o);
            }
        }

        // ---- Online softmax in exp2 domain (logits pre-scaled by log2e) ----
        float mx0 = -1e30f, mx1 = -1e30f;
#pragma unroll
        for (int nt = 0; nt < 8; nt++) {
            mx0 = fmaxf(mx0, fmaxf(Sc[nt][0], Sc[nt][1]));
            mx1 = fmaxf(mx1, fmaxf(Sc[nt][2], Sc[nt][3]));
        }
        mx0 = fmaxf(mx0, __shfl_xor_sync(0xFFFFFFFFu, mx0, 1));
        mx0 = fmaxf(mx0, __shfl_xor_sync(0xFFFFFFFFu, mx0, 2));
        mx1 = fmaxf(mx1, __shfl_xor_sync(0xFFFFFFFFu, mx1, 1));
        mx1 = fmaxf(mx1, __shfl_xor_sync(0xFFFFFFFFu, mx1, 2));

        float mn0 = fmaxf(m0, mx0), mn1 = fmaxf(m1, mx1);
        float f0 = exp2f(m0 - mn0), f1 = exp2f(m1 - mn1);

        float s0 = 0.f, s1 = 0.f;
#pragma unroll
        for (int nt = 0; nt < 8; nt++) {
            Sc[nt][0] = exp2f(Sc[nt][0] - mn0); s0 += Sc[nt][0];
            Sc[nt][1] = exp2f(Sc[nt][1] - mn0); s0 += Sc[nt][1];
            Sc[nt][2] = exp2f(Sc[nt][2] - mn1); s1 += Sc[nt][2];
            Sc[nt][3] = exp2f(Sc[nt][3] - mn1); s1 += Sc[nt][3];
        }
        s0 += __shfl_xor_sync(0xFFFFFFFFu, s0, 1);
        s0 += __shfl_xor_sync(0xFFFFFFFFu, s0, 2);
        s1 += __shfl_xor_sync(0xFFFFFFFFu, s1, 1);
        s1 += __shfl_xor_sync(0xFFFFFFFFu, s1, 2);

        l0 = l0 * f0 + s0;  l1 = l1 * f1 + s1;
        m0 = mn0;           m1 = mn1;

#pragma unroll
        for (int nt = 0; nt < 8; nt++) {
            O[nt][0] *= f0; O[nt][1] *= f0;
            O[nt][2] *= f1; O[nt][3] *= f1;
        }

        // ---- O += P V : pack Sc pairs into fp16 A-frags; VT via ldsm ----
#pragma unroll
        for (int j = 0; j < 4; j++) {           // k-chunks of 16 keys
            unsigned a0 = packh2(Sc[2 * j][0],     Sc[2 * j][1]);
            unsigned a1 = packh2(Sc[2 * j][2],     Sc[2 * j][3]);
            unsigned a2 = packh2(Sc[2 * j + 1][0], Sc[2 * j + 1][1]);
            unsigned a3 = packh2(Sc[2 * j + 1][2], Sc[2 * j + 1][3]);
#pragma unroll
            for (int np = 0; np < 4; np++) {    // dh-groups of 16
                unsigned b0e, b0o, b1e, b1o;
                ldsm4(b0e, b0o, b1e, b1o,
                      vBase + ((np * 16 + m_row) * VTSTR + j * 16 + m_col) * 2);
                mma_f16(O[2 * np],     a0, a1, a2, a3, b0e, b1e);
                mma_f16(O[2 * np + 1], a0, a1, a2, a3, b0o, b1o);
            }
        }
    }

    // ---- Epilogue: O /= l, write [B, N, E] (float2 stores, fp32) ----
    float li0 = 1.f / l0, li1 = 1.f / l1;
    int n_lo = qbase + r0 + g;
    int n_hi = n_lo + 8;
    float* out_lo = out + ((size_t)b * SEQ + n_lo) * EMBED + h * HEAD_DIM;
    float* out_hi = out + ((size_t)b * SEQ + n_hi) * EMBED + h * HEAD_DIM;
#pragma unroll
    for (int nt = 0; nt < 8; nt++) {
        int d = nt * 8 + 2 * t;
        float2 v0; v0.x = O[nt][0] * li0; v0.y = O[nt][1] * li0;
        float2 v1; v1.x = O[nt][2] * li1; v1.y = O[nt][3] * li1;
        *(float2*)&out_lo[d] = v0;
        *(float2*)&out_hi[d] = v1;
    }
}

extern "C" void kernel_launch(void* const* d_in, const int* in_sizes, int n_in,
                              void* d_out, int out_size)
{
    const float* query = (const float*)d_in[0];
    const float* key   = (const float*)d_in[1];
    const float* value = (const float*)d_in[2];
    const float* Wq = (const float*)d_in[3];
    const float* bq = (const float*)d_in[4];
    const float* Wk = (const float*)d_in[5];
    const float* bk = (const float*)d_in[6];
    const float* Wv = (const float*)d_in[7];
    const float* bv = (const float*)d_in[8];
    float* out = (float*)d_out;

    (void)in_sizes; (void)n_in; (void)out_size;

    __half *xr, *wr;
    cudaGetSymbolAddress((void**)&xr, g_xr);
    cudaGetSymbolAddress((void**)&wr, g_wr);

    // Stage 0: fp16 prepass — 2 launches (3 X tensors, 3 W tensors)
    const int NX4 = MTOT * EMBED / 4, NW4 = EMBED * EMBED / 4;
    {
        dim3 gx(1024, 3);
        cvt3_kernel<<<gx, 256>>>((const float4*)query, (const float4*)key, (const float4*)value,
                                 (uint2*)(xr + 0 * (size_t)MTOT * EMBED),
                                 (uint2*)(xr + 1 * (size_t)MTOT * EMBED),
                                 (uint2*)(xr + 2 * (size_t)MTOT * EMBED), NX4);
        dim3 gw(512, 3);
        cvt3_kernel<<<gw, 256>>>((const float4*)Wq, (const float4*)Wk, (const float4*)Wv,
                                 (uint2*)(wr + 0 * (size_t)EMBED * EMBED),
                                 (uint2*)(wr + 1 * (size_t)EMBED * EMBED),
                                 (uint2*)(wr + 2 * (size_t)EMBED * EMBED), NW4);
    }

    cudaFuncSetAttribute(qkv_gemm_kernel, cudaFuncAttributeMaxDynamicSharedMemorySize,
                         (int)QKV_SMEM);
    cudaFuncSetAttribute(attn_kernel, cudaFuncAttributeMaxDynamicSharedMemorySize,
                         (int)ATTN_SMEM);

    // Stage A: QKV projections (z = 0/1/2 -> q/k/vt)
    dim3 ggrid(EMBED / 128, MTOT / 128, 3);
    qkv_gemm_kernel<<<ggrid, 256, QKV_SMEM>>>(bq, bk, bv);

    // Stage B: flash attention
    dim3 agrid(SEQ / 128, HEADS, BATCH);
    attn_kernel<<<agrid, 256, ATTN_SMEM>>>(out);
}